// round 5
// baseline (speedup 1.0000x reference)
#include <cuda_runtime.h>
#include <math.h>

#define BS     32
#define GRID_N 2704
#define A_N    3
#define CH     85
#define VDIM   1024
#define HDIM   512
#define SEL    32
#define ROWS   (BS * SEL)          // 1024 flattened rows
#define EPSF   1e-8f

// ---------------- device scratch (static, no allocation) ----------------
__device__ int   g_idx[BS * SEL];
__device__ float g_isel[(size_t)ROWS * VDIM];
__device__ float g_vis[(size_t)ROWS * HDIM];
__device__ float g_w[ROWS * 2];
__device__ float g_vis2[(size_t)ROWS * HDIM];
__device__ float g_lang[BS * HDIM];
__device__ float g_ln[BS];

// ---------------- K1: objectness score + exact top-32 via histogram ------
__global__ void topk_kernel(const float* __restrict__ boxes) {
    int b = blockIdx.x;
    int tid = threadIdx.x;          // 256 threads
    __shared__ float sc[GRID_N];
    __shared__ int   hist[512];
    __shared__ int   s_binB, s_definite;
    __shared__ int   cnt_hi, cnt_cb, overflow;
    __shared__ int   hi_idx[SEL];
    __shared__ float cb_sc[512];
    __shared__ int   cb_idx[512];
    __shared__ int   sel[SEL];
    __shared__ float rv[8];
    __shared__ int   ri[8];

    for (int i = tid; i < 512; i += 256) hist[i] = 0;
    if (tid == 0) { cnt_hi = 0; cnt_cb = 0; overflow = 0; }
    __syncthreads();

    const float* bb = boxes + (size_t)b * GRID_N * A_N * CH;
    for (int g = tid; g < GRID_N; g += 256) {
        const float* p = bb + (size_t)g * A_N * CH;
        float s = (p[4] + p[CH + 4] + p[2 * CH + 4]) * (1.0f / 3.0f);
        sc[g] = s;
        int bin = (int)(s * 512.0f);
        bin = max(0, min(511, bin));
        atomicAdd(&hist[bin], 1);
    }
    __syncthreads();

    if (tid == 0) {
        int cum = 0, bB = 0, def = 0;
        for (int v = 511; v >= 0; v--) {
            cum += hist[v];
            if (cum >= SEL) { bB = v; def = cum - hist[v]; break; }
        }
        s_binB = bB; s_definite = def;
    }
    __syncthreads();
    int binB = s_binB;

    for (int g = tid; g < GRID_N; g += 256) {
        float s = sc[g];
        int bin = (int)(s * 512.0f);
        bin = max(0, min(511, bin));
        if (bin > binB) {
            int p = atomicAdd(&cnt_hi, 1);
            hi_idx[p] = g;
        } else if (bin == binB) {
            int p = atomicAdd(&cnt_cb, 1);
            if (p < 512) { cb_sc[p] = s; cb_idx[p] = g; }
            else overflow = 1;
        }
    }
    __syncthreads();

    if (!overflow) {
        if (tid >= 32 && (tid - 32) < s_definite) sel[tid - 32] = hi_idx[tid - 32];
        if (tid < 32) {
            int need = SEL - s_definite;
            int n = min(cnt_cb, 512);
            for (int it = 0; it < need; it++) {
                float best = -1e30f; int bi = GRID_N;
                for (int c = tid; c < n; c += 32) {
                    float v = cb_sc[c]; int gi = cb_idx[c];
                    if (v > best || (v == best && gi < bi)) { best = v; bi = gi; }
                }
                #pragma unroll
                for (int o = 16; o; o >>= 1) {
                    float ov = __shfl_down_sync(0xffffffffu, best, o);
                    int   oi = __shfl_down_sync(0xffffffffu, bi, o);
                    if (ov > best || (ov == best && oi < bi)) { best = ov; bi = oi; }
                }
                bi = __shfl_sync(0xffffffffu, bi, 0);
                if (tid == 0) sel[s_definite + it] = bi;
                for (int c = tid; c < n; c += 32)
                    if (cb_idx[c] == bi) cb_sc[c] = -1e30f;
                __syncwarp();
            }
        }
    }
    __syncthreads();

    if (overflow) {
        for (int it = 0; it < SEL; it++) {
            float best = -1e30f;
            int   bi = GRID_N;
            for (int g = tid; g < GRID_N; g += 256) {
                float v = sc[g];
                if (v > best) { best = v; bi = g; }
            }
            #pragma unroll
            for (int o = 16; o; o >>= 1) {
                float ov = __shfl_down_sync(0xffffffffu, best, o);
                int   oi = __shfl_down_sync(0xffffffffu, bi, o);
                if (ov > best || (ov == best && oi < bi)) { best = ov; bi = oi; }
            }
            if ((tid & 31) == 0) { rv[tid >> 5] = best; ri[tid >> 5] = bi; }
            __syncthreads();
            if (tid == 0) {
                float B = rv[0]; int BI = ri[0];
                for (int w = 1; w < 8; w++)
                    if (rv[w] > B || (rv[w] == B && ri[w] < BI)) { B = rv[w]; BI = ri[w]; }
                sel[it] = BI;
                sc[BI] = -1e30f;
            }
            __syncthreads();
        }
    }

    if (tid == 0) {
        for (int i = 1; i < SEL; i++) {
            int v = sel[i], j = i - 1;
            while (j >= 0 && sel[j] > v) { sel[j + 1] = sel[j]; j--; }
            sel[j + 1] = v;
        }
        for (int i = 0; i < SEL; i++) g_idx[b * SEL + i] = sel[i];
    }
}

// ---------------- K2: gather selected feature columns --------------------
__global__ void gather_kernel(const float* __restrict__ xfeat) {
    int row = blockIdx.x;           // b*SEL + s
    int b = row >> 5;
    int g = g_idx[row];
    const float* src = xfeat + (size_t)b * VDIM * GRID_N + g;
    float* dst = g_isel + (size_t)row * VDIM;
    for (int v = threadIdx.x; v < VDIM; v += blockDim.x)
        dst[v] = __ldg(&src[(size_t)v * GRID_N]);
}

// ---------------- K3: vis = isel @ W_vs + b_vs (flat 1024x512 GEMM) ------
// 64x64 tile, BK=32, 128 threads, 4(M)x8(N) per thread, double buffered.
#define G1_BK 32
#define G1_NT (VDIM / G1_BK)
__global__ __launch_bounds__(128) void gemm1_kernel(const float* __restrict__ W,
                                                    const float* __restrict__ bias) {
    int mBase = blockIdx.y * 64;
    int nBase = blockIdx.x * 64;
    int tid = threadIdx.x;
    int tx = tid & 7;               // n0 = tx*8
    int ty = tid >> 3;              // m0 = ty*4

    __shared__ float Xs[2][64 * 36];                  // [m][k] pad 36
    __shared__ __align__(16) float Ws[2][G1_BK * 64]; // [k][n]

    const float* Ab = g_isel;

    // load indices (4 float4 each for A and W per tile)
    float4 rA[4], rW[4];
    #pragma unroll
    for (int i = 0; i < 4; i++) {
        int l = tid + i * 128;
        int a_m = l >> 3, a_k = (l & 7) * 4;
        rA[i] = *(const float4*)&Ab[(size_t)(mBase + a_m) * VDIM + a_k];
    }
    #pragma unroll
    for (int i = 0; i < 4; i++) {
        int l = tid + i * 128;
        int w_k = l >> 4, w_n = (l & 15) * 4;
        rW[i] = *(const float4*)&W[(size_t)w_k * HDIM + nBase + w_n];
    }
    #pragma unroll
    for (int i = 0; i < 4; i++) {
        int l = tid + i * 128;
        int a_m = l >> 3, a_k = (l & 7) * 4;
        *(float4*)&Xs[0][a_m * 36 + a_k] = rA[i];
    }
    #pragma unroll
    for (int i = 0; i < 4; i++) {
        int l = tid + i * 128;
        int w_k = l >> 4, w_n = (l & 15) * 4;
        *(float4*)&Ws[0][w_k * 64 + w_n] = rW[i];
    }
    __syncthreads();

    float acc[4][8];
    #pragma unroll
    for (int i = 0; i < 4; i++)
        #pragma unroll
        for (int j = 0; j < 8; j++) acc[i][j] = 0.f;

    for (int t = 0; t < G1_NT; t++) {
        int cur = t & 1;
        int k0n = (t + 1) * G1_BK;
        if (t + 1 < G1_NT) {
            #pragma unroll
            for (int i = 0; i < 4; i++) {
                int l = tid + i * 128;
                int a_m = l >> 3, a_k = (l & 7) * 4;
                rA[i] = *(const float4*)&Ab[(size_t)(mBase + a_m) * VDIM + k0n + a_k];
            }
            #pragma unroll
            for (int i = 0; i < 4; i++) {
                int l = tid + i * 128;
                int w_k = l >> 4, w_n = (l & 15) * 4;
                rW[i] = *(const float4*)&W[(size_t)(k0n + w_k) * HDIM + nBase + w_n];
            }
        }
        #pragma unroll
        for (int k = 0; k < G1_BK; k++) {
            float4 w0 = *(const float4*)&Ws[cur][k * 64 + tx * 8];
            float4 w1 = *(const float4*)&Ws[cur][k * 64 + tx * 8 + 4];
            float x0 = Xs[cur][(ty * 4 + 0) * 36 + k];
            float x1 = Xs[cur][(ty * 4 + 1) * 36 + k];
            float x2 = Xs[cur][(ty * 4 + 2) * 36 + k];
            float x3 = Xs[cur][(ty * 4 + 3) * 36 + k];
            acc[0][0] += x0 * w0.x; acc[0][1] += x0 * w0.y; acc[0][2] += x0 * w0.z; acc[0][3] += x0 * w0.w;
            acc[0][4] += x0 * w1.x; acc[0][5] += x0 * w1.y; acc[0][6] += x0 * w1.z; acc[0][7] += x0 * w1.w;
            acc[1][0] += x1 * w0.x; acc[1][1] += x1 * w0.y; acc[1][2] += x1 * w0.z; acc[1][3] += x1 * w0.w;
            acc[1][4] += x1 * w1.x; acc[1][5] += x1 * w1.y; acc[1][6] += x1 * w1.z; acc[1][7] += x1 * w1.w;
            acc[2][0] += x2 * w0.x; acc[2][1] += x2 * w0.y; acc[2][2] += x2 * w0.z; acc[2][3] += x2 * w0.w;
            acc[2][4] += x2 * w1.x; acc[2][5] += x2 * w1.y; acc[2][6] += x2 * w1.z; acc[2][7] += x2 * w1.w;
            acc[3][0] += x3 * w0.x; acc[3][1] += x3 * w0.y; acc[3][2] += x3 * w0.z; acc[3][3] += x3 * w0.w;
            acc[3][4] += x3 * w1.x; acc[3][5] += x3 * w1.y; acc[3][6] += x3 * w1.z; acc[3][7] += x3 * w1.w;
        }
        if (t + 1 < G1_NT) {
            int nx = cur ^ 1;
            #pragma unroll
            for (int i = 0; i < 4; i++) {
                int l = tid + i * 128;
                int a_m = l >> 3, a_k = (l & 7) * 4;
                *(float4*)&Xs[nx][a_m * 36 + a_k] = rA[i];
            }
            #pragma unroll
            for (int i = 0; i < 4; i++) {
                int l = tid + i * 128;
                int w_k = l >> 4, w_n = (l & 15) * 4;
                *(float4*)&Ws[nx][w_k * 64 + w_n] = rW[i];
            }
        }
        __syncthreads();
    }

    float4 bv0 = *(const float4*)&bias[nBase + tx * 8];
    float4 bv1 = *(const float4*)&bias[nBase + tx * 8 + 4];
    #pragma unroll
    for (int i = 0; i < 4; i++) {
        int row = mBase + ty * 4 + i;
        float4 o0, o1;
        o0.x = acc[i][0] + bv0.x; o0.y = acc[i][1] + bv0.y;
        o0.z = acc[i][2] + bv0.z; o0.w = acc[i][3] + bv0.w;
        o1.x = acc[i][4] + bv1.x; o1.y = acc[i][5] + bv1.y;
        o1.z = acc[i][6] + bv1.z; o1.w = acc[i][7] + bv1.w;
        *(float4*)&g_vis[(size_t)row * HDIM + nBase + tx * 8] = o0;
        *(float4*)&g_vis[(size_t)row * HDIM + nBase + tx * 8 + 4] = o1;
    }
}

// ---------------- K4: gate logits (2 warps per row) ----------------------
__global__ __launch_bounds__(256) void wsoft_kernel(const float* __restrict__ tag,
                                                    const float* __restrict__ pos,
                                                    const float* __restrict__ Wsoft,
                                                    const float* __restrict__ bsoft) {
    int tid = threadIdx.x;
    int w = tid >> 5, lane = tid & 31;
    int rb = blockIdx.x * 4;                 // 256 blocks, 4 rows each
    int r = rb + (w >> 1);
    int half = w & 1;
    __shared__ float pl[8][2];

    const float4* v = (const float4*)(g_vis + (size_t)r * HDIM);
    const float4* t = (const float4*)(tag + (size_t)r * HDIM);
    const float4* p = (const float4*)(pos + (size_t)r * HDIM);
    const float4* Wq = (const float4*)Wsoft;
    float l0 = 0.f, l1 = 0.f;
    #pragma unroll
    for (int i = 0; i < 2; i++) {
        int h4 = half * 64 + i * 32 + lane;
        float4 a = v[h4], c = t[h4], e = p[h4];
        float s0 = a.x + c.x + e.x, s1 = a.y + c.y + e.y;
        float s2 = a.z + c.z + e.z, s3 = a.w + c.w + e.w;
        float4 w01 = Wq[h4 * 2], w23 = Wq[h4 * 2 + 1];
        l0 += s0 * w01.x + s1 * w01.z + s2 * w23.x + s3 * w23.z;
        l1 += s0 * w01.y + s1 * w01.w + s2 * w23.y + s3 * w23.w;
    }
    #pragma unroll
    for (int o = 16; o; o >>= 1) {
        l0 += __shfl_xor_sync(0xffffffffu, l0, o);
        l1 += __shfl_xor_sync(0xffffffffu, l1, o);
    }
    if (lane == 0) { pl[w][0] = l0; pl[w][1] = l1; }
    __syncthreads();
    if (tid < 4) {
        int rr = rb + tid;
        float L0 = pl[tid * 2][0] + pl[tid * 2 + 1][0];
        float L1 = pl[tid * 2][1] + pl[tid * 2 + 1][1];
        L0 = (L0 + bsoft[0]) / 0.03f;
        L1 = (L1 + bsoft[1]) / 0.03f;
        float m = fmaxf(L0, L1);
        float lse = m + logf(expf(L0 - m) + expf(L1 - m));
        g_w[2 * rr + 0] = L0 - lse;
        g_w[2 * rr + 1] = L1 - lse;
    }
}

// ---------------- K5: vis2 (flat, dual-stream GEMM, 64x64, BK=16) --------
#define G2_BK 16
#define G2_NT (HDIM / G2_BK)
__global__ __launch_bounds__(128) void gemm2_kernel(
    const float* __restrict__ Wvp, const float* __restrict__ bvp,
    const float* __restrict__ Wtg, const float* __restrict__ btg,
    const float* __restrict__ tag, const float* __restrict__ pos) {
    int mBase = blockIdx.y * 64;
    int nBase = blockIdx.x * 64;
    int tid = threadIdx.x;
    int tx = tid & 7;
    int ty = tid >> 3;

    __shared__ float Xs[2][64 * 20], Ys[2][64 * 20];   // [m][k] pad 20
    __shared__ __align__(16) float Ws[2][G2_BK * 64];
    __shared__ __align__(16) float Vs[2][G2_BK * 64];
    __shared__ float w0s[64], w1s[64];

    if (tid < 64) {
        w0s[tid] = g_w[(mBase + tid) * 2 + 0];
        w1s[tid] = g_w[(mBase + tid) * 2 + 1];
    }

    const float* Xb = g_vis;
    const float* Yb = tag;

    float4 rX[2], rY[2], rW[2], rV[2];
    #pragma unroll
    for (int i = 0; i < 2; i++) {
        int l = tid + i * 128;
        int a_m = l >> 2, a_k = (l & 3) * 4;
        rX[i] = *(const float4*)&Xb[(size_t)(mBase + a_m) * HDIM + a_k];
        rY[i] = *(const float4*)&Yb[(size_t)(mBase + a_m) * HDIM + a_k];
    }
    #pragma unroll
    for (int i = 0; i < 2; i++) {
        int l = tid + i * 128;
        int w_k = l >> 4, w_n = (l & 15) * 4;
        rW[i] = *(const float4*)&Wvp[(size_t)w_k * HDIM + nBase + w_n];
        rV[i] = *(const float4*)&Wtg[(size_t)w_k * HDIM + nBase + w_n];
    }
    __syncthreads();    // w0s/w1s visible

    #pragma unroll
    for (int i = 0; i < 2; i++) {
        int l = tid + i * 128;
        int a_m = l >> 2, a_k = (l & 3) * 4;
        float s0 = w0s[a_m], s1 = w1s[a_m];
        float4 x = rX[i], y = rY[i];
        x.x *= s0; x.y *= s0; x.z *= s0; x.w *= s0;
        y.x *= s1; y.y *= s1; y.z *= s1; y.w *= s1;
        *(float4*)&Xs[0][a_m * 20 + a_k] = x;
        *(float4*)&Ys[0][a_m * 20 + a_k] = y;
    }
    #pragma unroll
    for (int i = 0; i < 2; i++) {
        int l = tid + i * 128;
        int w_k = l >> 4, w_n = (l & 15) * 4;
        *(float4*)&Ws[0][w_k * 64 + w_n] = rW[i];
        *(float4*)&Vs[0][w_k * 64 + w_n] = rV[i];
    }
    __syncthreads();

    float acc[4][8];
    #pragma unroll
    for (int i = 0; i < 4; i++)
        #pragma unroll
        for (int j = 0; j < 8; j++) acc[i][j] = 0.f;

    for (int t = 0; t < G2_NT; t++) {
        int cur = t & 1;
        int k0n = (t + 1) * G2_BK;
        if (t + 1 < G2_NT) {
            #pragma unroll
            for (int i = 0; i < 2; i++) {
                int l = tid + i * 128;
                int a_m = l >> 2, a_k = (l & 3) * 4;
                rX[i] = *(const float4*)&Xb[(size_t)(mBase + a_m) * HDIM + k0n + a_k];
                rY[i] = *(const float4*)&Yb[(size_t)(mBase + a_m) * HDIM + k0n + a_k];
            }
            #pragma unroll
            for (int i = 0; i < 2; i++) {
                int l = tid + i * 128;
                int w_k = l >> 4, w_n = (l & 15) * 4;
                rW[i] = *(const float4*)&Wvp[(size_t)(k0n + w_k) * HDIM + nBase + w_n];
                rV[i] = *(const float4*)&Wtg[(size_t)(k0n + w_k) * HDIM + nBase + w_n];
            }
        }
        #pragma unroll
        for (int k = 0; k < G2_BK; k++) {
            float4 wv0 = *(const float4*)&Ws[cur][k * 64 + tx * 8];
            float4 wv1 = *(const float4*)&Ws[cur][k * 64 + tx * 8 + 4];
            float4 vv0 = *(const float4*)&Vs[cur][k * 64 + tx * 8];
            float4 vv1 = *(const float4*)&Vs[cur][k * 64 + tx * 8 + 4];
            #pragma unroll
            for (int i = 0; i < 4; i++) {
                float x = Xs[cur][(ty * 4 + i) * 20 + k];
                float y = Ys[cur][(ty * 4 + i) * 20 + k];
                acc[i][0] += x * wv0.x + y * vv0.x;
                acc[i][1] += x * wv0.y + y * vv0.y;
                acc[i][2] += x * wv0.z + y * vv0.z;
                acc[i][3] += x * wv0.w + y * vv0.w;
                acc[i][4] += x * wv1.x + y * vv1.x;
                acc[i][5] += x * wv1.y + y * vv1.y;
                acc[i][6] += x * wv1.z + y * vv1.z;
                acc[i][7] += x * wv1.w + y * vv1.w;
            }
        }
        if (t + 1 < G2_NT) {
            int nx = cur ^ 1;
            #pragma unroll
            for (int i = 0; i < 2; i++) {
                int l = tid + i * 128;
                int a_m = l >> 2, a_k = (l & 3) * 4;
                float s0 = w0s[a_m], s1 = w1s[a_m];
                float4 x = rX[i], y = rY[i];
                x.x *= s0; x.y *= s0; x.z *= s0; x.w *= s0;
                y.x *= s1; y.y *= s1; y.z *= s1; y.w *= s1;
                *(float4*)&Xs[nx][a_m * 20 + a_k] = x;
                *(float4*)&Ys[nx][a_m * 20 + a_k] = y;
            }
            #pragma unroll
            for (int i = 0; i < 2; i++) {
                int l = tid + i * 128;
                int w_k = l >> 4, w_n = (l & 15) * 4;
                *(float4*)&Ws[nx][w_k * 64 + w_n] = rW[i];
                *(float4*)&Vs[nx][w_k * 64 + w_n] = rV[i];
            }
        }
        __syncthreads();
    }

    int col = nBase + tx * 8;
    float4 b0, b1;
    {
        float4 a0 = *(const float4*)&bvp[col];
        float4 a1 = *(const float4*)&bvp[col + 4];
        float4 c0 = *(const float4*)&btg[col];
        float4 c1 = *(const float4*)&btg[col + 4];
        b0.x = a0.x + c0.x; b0.y = a0.y + c0.y; b0.z = a0.z + c0.z; b0.w = a0.w + c0.w;
        b1.x = a1.x + c1.x; b1.y = a1.y + c1.y; b1.z = a1.z + c1.z; b1.w = a1.w + c1.w;
    }
    #pragma unroll
    for (int i = 0; i < 4; i++) {
        int row = mBase + ty * 4 + i;
        float4 p0 = *(const float4*)&pos[(size_t)row * HDIM + col];
        float4 p1 = *(const float4*)&pos[(size_t)row * HDIM + col + 4];
        float4 o0, o1;
        o0.x = acc[i][0] + b0.x + p0.x; o0.y = acc[i][1] + b0.y + p0.y;
        o0.z = acc[i][2] + b0.z + p0.z; o0.w = acc[i][3] + b0.w + p0.w;
        o1.x = acc[i][4] + b1.x + p1.x; o1.y = acc[i][5] + b1.y + p1.y;
        o1.z = acc[i][6] + b1.z + p1.z; o1.w = acc[i][7] + b1.w + p1.w;
        *(float4*)&g_vis2[(size_t)row * HDIM + col] = o0;
        *(float4*)&g_vis2[(size_t)row * HDIM + col + 4] = o1;
    }
}

// ---------------- K6: language projection + norm (512 thr/blk) -----------
__global__ __launch_bounds__(512) void lang_kernel(const float* __restrict__ lang,
                                                   const float* __restrict__ Wts,
                                                   const float* __restrict__ bts) {
    int b = blockIdx.x, tid = threadIdx.x;   // 512 threads, one output each
    __shared__ float lg[HDIM];
    __shared__ float wr[16];
    lg[tid] = lang[b * HDIM + tid];
    __syncthreads();
    float a = bts[tid];
    #pragma unroll 8
    for (int k = 0; k < HDIM; k++)
        a += lg[k] * Wts[(size_t)k * HDIM + tid];
    g_lang[b * HDIM + tid] = a;
    float q = a * a;
    #pragma unroll
    for (int o = 16; o; o >>= 1) q += __shfl_xor_sync(0xffffffffu, q, o);
    if ((tid & 31) == 0) wr[tid >> 5] = q;
    __syncthreads();
    if (tid < 32) {
        float s = (tid < 16) ? wr[tid] : 0.f;
        #pragma unroll
        for (int o = 8; o; o >>= 1) s += __shfl_xor_sync(0xffffffffu, s, o);
        if (tid == 0) g_ln[b] = sqrtf(s) + EPSF;
    }
}

// ---------------- K7: cosine sim (warp per sel), argmax, box decode ------
__global__ void final_kernel(const float* __restrict__ boxes, float* __restrict__ out) {
    int b = blockIdx.x, tid = threadIdx.x;   // 1024 threads = 32 warps
    int w = tid >> 5, lane = tid & 31;
    __shared__ float ssim[SEL];

    const float4* v2 = (const float4*)(g_vis2 + (size_t)(b * SEL + w) * HDIM);
    const float4* le = (const float4*)(g_lang + (size_t)b * HDIM);
    float d = 0.f, q = 0.f;
    #pragma unroll
    for (int i = 0; i < 4; i++) {
        float4 a = v2[lane + i * 32];
        float4 c = le[lane + i * 32];
        d += a.x * c.x + a.y * c.y + a.z * c.z + a.w * c.w;
        q += a.x * a.x + a.y * a.y + a.z * a.z + a.w * a.w;
    }
    #pragma unroll
    for (int o = 16; o; o >>= 1) {
        d += __shfl_xor_sync(0xffffffffu, d, o);
        q += __shfl_xor_sync(0xffffffffu, q, o);
    }
    if (lane == 0) ssim[w] = d / ((sqrtf(q) + EPSF) * g_ln[b]);
    __syncthreads();

    if (tid < SEL) out[BS * 5 + b * SEL + tid] = ssim[tid];

    if (w == 0) {
        float v = ssim[lane]; int bi = lane;
        #pragma unroll
        for (int o = 16; o; o >>= 1) {
            float ov = __shfl_down_sync(0xffffffffu, v, o);
            int   oi = __shfl_down_sync(0xffffffffu, bi, o);
            if (ov > v || (ov == v && oi < bi)) { v = ov; bi = oi; }
        }
        if (lane == 0) {
            int g = g_idx[b * SEL + bi];
            const float* base = boxes + ((size_t)b * GRID_N + g) * A_N * CH;
            int j = 0; float ov = base[4];
            for (int a = 1; a < A_N; a++) {
                float o2 = base[a * CH + 4];
                if (o2 > ov) { ov = o2; j = a; }
            }
            float x = base[j * CH + 0], y = base[j * CH + 1];
            float wd = base[j * CH + 2], hh = base[j * CH + 3];
            float x1 = x - wd * 0.5f, y1 = y - hh * 0.5f;
            out[b * 5 + 0] = x1;
            out[b * 5 + 1] = y1;
            out[b * 5 + 2] = x1 + wd;
            out[b * 5 + 3] = y1 + hh;
            out[b * 5 + 4] = ov;
        }
    }
}

// ---------------- launch --------------------------------------------------
extern "C" void kernel_launch(void* const* d_in, const int* in_sizes, int n_in,
                              void* d_out, int out_size) {
    const float* boxes    = (const float*)d_in[0];
    const float* x_feat   = (const float*)d_in[1];
    const float* tag_emb  = (const float*)d_in[2];
    const float* pos_emb  = (const float*)d_in[3];
    const float* lang     = (const float*)d_in[4];
    const float* W_vs     = (const float*)d_in[5];
    const float* b_vs     = (const float*)d_in[6];
    const float* W_ts     = (const float*)d_in[7];
    const float* b_ts     = (const float*)d_in[8];
    const float* W_vs_pos = (const float*)d_in[9];
    const float* b_vs_pos = (const float*)d_in[10];
    const float* W_tag    = (const float*)d_in[11];
    const float* b_tag    = (const float*)d_in[12];
    const float* W_soft   = (const float*)d_in[13];
    const float* b_soft   = (const float*)d_in[14];
    float* out = (float*)d_out;

    topk_kernel<<<BS, 256>>>(boxes);
    gather_kernel<<<BS * SEL, 256>>>(x_feat);
    lang_kernel<<<BS, 512>>>(lang, W_ts, b_ts);
    gemm1_kernel<<<dim3(HDIM / 64, ROWS / 64), 128>>>(W_vs, b_vs);
    wsoft_kernel<<<ROWS / 4, 256>>>(tag_emb, pos_emb, W_soft, b_soft);
    gemm2_kernel<<<dim3(HDIM / 64, ROWS / 64), 128>>>(W_vs_pos, b_vs_pos, W_tag, b_tag, tag_emb, pos_emb);
    final_kernel<<<BS, 1024>>>(boxes, out);
}

// round 6
// speedup vs baseline: 1.2361x; 1.2361x over previous
#include <cuda_runtime.h>
#include <math.h>

#define BS     32
#define GRID_N 2704
#define A_N    3
#define CH     85
#define VDIM   1024
#define HDIM   512
#define SEL    32
#define ROWS   (BS * SEL)          // 1024 flattened rows
#define EPSF   1e-8f

// ---------------- device scratch (static, no allocation) ----------------
__device__ int   g_idx[BS * SEL];
__device__ float g_isel[(size_t)ROWS * VDIM];
__device__ float g_vis[(size_t)ROWS * HDIM];
__device__ float g_w[ROWS * 2];
__device__ float g_vis2[(size_t)ROWS * HDIM];
__device__ float g_lang[BS * HDIM];
__device__ float g_ln[BS];

// ---------------- K1: objectness score + exact top-32 via histogram ------
__global__ void topk_kernel(const float* __restrict__ boxes) {
    int b = blockIdx.x;
    int tid = threadIdx.x;          // 256 threads
    __shared__ float sc[GRID_N];
    __shared__ int   hist[512];
    __shared__ int   s_binB, s_definite;
    __shared__ int   cnt_hi, cnt_cb, overflow;
    __shared__ int   hi_idx[SEL];
    __shared__ float cb_sc[512];
    __shared__ int   cb_idx[512];
    __shared__ int   sel[SEL];
    __shared__ float rv[8];
    __shared__ int   ri[8];

    for (int i = tid; i < 512; i += 256) hist[i] = 0;
    if (tid == 0) { cnt_hi = 0; cnt_cb = 0; overflow = 0; }
    __syncthreads();

    const float* bb = boxes + (size_t)b * GRID_N * A_N * CH;
    for (int g = tid; g < GRID_N; g += 256) {
        const float* p = bb + (size_t)g * A_N * CH;
        float s = (p[4] + p[CH + 4] + p[2 * CH + 4]) * (1.0f / 3.0f);
        sc[g] = s;
        int bin = (int)(s * 512.0f);
        bin = max(0, min(511, bin));
        atomicAdd(&hist[bin], 1);
    }
    __syncthreads();

    if (tid == 0) {
        int cum = 0, bB = 0, def = 0;
        for (int v = 511; v >= 0; v--) {
            cum += hist[v];
            if (cum >= SEL) { bB = v; def = cum - hist[v]; break; }
        }
        s_binB = bB; s_definite = def;
    }
    __syncthreads();
    int binB = s_binB;

    for (int g = tid; g < GRID_N; g += 256) {
        float s = sc[g];
        int bin = (int)(s * 512.0f);
        bin = max(0, min(511, bin));
        if (bin > binB) {
            int p = atomicAdd(&cnt_hi, 1);
            hi_idx[p] = g;
        } else if (bin == binB) {
            int p = atomicAdd(&cnt_cb, 1);
            if (p < 512) { cb_sc[p] = s; cb_idx[p] = g; }
            else overflow = 1;
        }
    }
    __syncthreads();

    if (!overflow) {
        if (tid >= 32 && (tid - 32) < s_definite) sel[tid - 32] = hi_idx[tid - 32];
        if (tid < 32) {
            int need = SEL - s_definite;
            int n = min(cnt_cb, 512);
            for (int it = 0; it < need; it++) {
                float best = -1e30f; int bi = GRID_N;
                for (int c = tid; c < n; c += 32) {
                    float v = cb_sc[c]; int gi = cb_idx[c];
                    if (v > best || (v == best && gi < bi)) { best = v; bi = gi; }
                }
                #pragma unroll
                for (int o = 16; o; o >>= 1) {
                    float ov = __shfl_down_sync(0xffffffffu, best, o);
                    int   oi = __shfl_down_sync(0xffffffffu, bi, o);
                    if (ov > best || (ov == best && oi < bi)) { best = ov; bi = oi; }
                }
                bi = __shfl_sync(0xffffffffu, bi, 0);
                if (tid == 0) sel[s_definite + it] = bi;
                for (int c = tid; c < n; c += 32)
                    if (cb_idx[c] == bi) cb_sc[c] = -1e30f;
                __syncwarp();
            }
        }
    }
    __syncthreads();

    if (overflow) {
        for (int it = 0; it < SEL; it++) {
            float best = -1e30f;
            int   bi = GRID_N;
            for (int g = tid; g < GRID_N; g += 256) {
                float v = sc[g];
                if (v > best) { best = v; bi = g; }
            }
            #pragma unroll
            for (int o = 16; o; o >>= 1) {
                float ov = __shfl_down_sync(0xffffffffu, best, o);
                int   oi = __shfl_down_sync(0xffffffffu, bi, o);
                if (ov > best || (ov == best && oi < bi)) { best = ov; bi = oi; }
            }
            if ((tid & 31) == 0) { rv[tid >> 5] = best; ri[tid >> 5] = bi; }
            __syncthreads();
            if (tid == 0) {
                float B = rv[0]; int BI = ri[0];
                for (int w = 1; w < 8; w++)
                    if (rv[w] > B || (rv[w] == B && ri[w] < BI)) { B = rv[w]; BI = ri[w]; }
                sel[it] = BI;
                sc[BI] = -1e30f;
            }
            __syncthreads();
        }
    }

    if (tid == 0) {
        for (int i = 1; i < SEL; i++) {
            int v = sel[i], j = i - 1;
            while (j >= 0 && sel[j] > v) { sel[j + 1] = sel[j]; j--; }
            sel[j + 1] = v;
        }
        for (int i = 0; i < SEL; i++) g_idx[b * SEL + i] = sel[i];
    }
}

// ---------------- K2: gather selected feature columns --------------------
__global__ void gather_kernel(const float* __restrict__ xfeat) {
    int row = blockIdx.x;           // b*SEL + s
    int b = row >> 5;
    int g = g_idx[row];
    const float* src = xfeat + (size_t)b * VDIM * GRID_N + g;
    float* dst = g_isel + (size_t)row * VDIM;
    for (int v = threadIdx.x; v < VDIM; v += blockDim.x)
        dst[v] = __ldg(&src[(size_t)v * GRID_N]);
}

// ---------------- K3: vis = isel @ W_vs + b_vs ---------------------------
// Tile M=32, N=64, BK=32. 128 threads, 4x4 per thread. All-float4 smem reads:
// A kept in natural [m][k] layout (stride 36 floats = 144B, 16B-aligned),
// k processed in chunks of 4 -> 8 LDS.128 per 64 FFMA.
#define G1_BK 32
#define G1_NT (VDIM / G1_BK)
#define XS_STRIDE 36
__global__ __launch_bounds__(128) void gemm1_kernel(const float* __restrict__ W,
                                                    const float* __restrict__ bias) {
    int mBase = blockIdx.y * 32;
    int nBase = blockIdx.x * 64;
    int tid = threadIdx.x;
    int tx = tid & 15;              // n0 = tx*4
    int ty = tid >> 4;              // m0 = ty*4

    __shared__ __align__(16) float Xs[2][32 * XS_STRIDE];
    __shared__ __align__(16) float Ws[2][G1_BK * 64];

    // A load: l = tid + i*128 (i=0..1): a_m = l>>3 (0..31), a_k = (l&7)*4
    int a_m = tid >> 3;
    int a_k = (tid & 7) * 4;
    // W load: l = tid + i*128 (i=0..3): w_k = (tid>>4) + i*8, w_n = (tid&15)*4
    int w_k = tid >> 4;
    int w_n = (tid & 15) * 4;

    const float* Ab = g_isel + (size_t)mBase * VDIM;

    float4 rA[2], rW[4];
    #pragma unroll
    for (int i = 0; i < 2; i++)
        rA[i] = *(const float4*)&Ab[(size_t)(a_m + i * 16) * VDIM + a_k];
    #pragma unroll
    for (int i = 0; i < 4; i++)
        rW[i] = *(const float4*)&W[(size_t)(w_k + i * 8) * HDIM + nBase + w_n];
    #pragma unroll
    for (int i = 0; i < 2; i++)
        *(float4*)&Xs[0][(a_m + i * 16) * XS_STRIDE + a_k] = rA[i];
    #pragma unroll
    for (int i = 0; i < 4; i++)
        *(float4*)&Ws[0][(w_k + i * 8) * 64 + w_n] = rW[i];
    __syncthreads();

    float acc[4][4];
    #pragma unroll
    for (int i = 0; i < 4; i++)
        #pragma unroll
        for (int j = 0; j < 4; j++) acc[i][j] = 0.f;

    for (int t = 0; t < G1_NT; t++) {
        int cur = t & 1;
        int k0n = (t + 1) * G1_BK;
        if (t + 1 < G1_NT) {
            #pragma unroll
            for (int i = 0; i < 2; i++)
                rA[i] = *(const float4*)&Ab[(size_t)(a_m + i * 16) * VDIM + k0n + a_k];
            #pragma unroll
            for (int i = 0; i < 4; i++)
                rW[i] = *(const float4*)&W[(size_t)(k0n + w_k + i * 8) * HDIM + nBase + w_n];
        }
        #pragma unroll
        for (int kc = 0; kc < G1_BK / 4; kc++) {
            float4 xv[4];
            #pragma unroll
            for (int i = 0; i < 4; i++)
                xv[i] = *(const float4*)&Xs[cur][(ty * 4 + i) * XS_STRIDE + kc * 4];
            #pragma unroll
            for (int j = 0; j < 4; j++) {
                float4 wv = *(const float4*)&Ws[cur][(kc * 4 + j) * 64 + tx * 4];
                #pragma unroll
                for (int i = 0; i < 4; i++) {
                    float x = (j == 0) ? xv[i].x : (j == 1) ? xv[i].y : (j == 2) ? xv[i].z : xv[i].w;
                    acc[i][0] += x * wv.x;
                    acc[i][1] += x * wv.y;
                    acc[i][2] += x * wv.z;
                    acc[i][3] += x * wv.w;
                }
            }
        }
        if (t + 1 < G1_NT) {
            int nx = cur ^ 1;
            #pragma unroll
            for (int i = 0; i < 2; i++)
                *(float4*)&Xs[nx][(a_m + i * 16) * XS_STRIDE + a_k] = rA[i];
            #pragma unroll
            for (int i = 0; i < 4; i++)
                *(float4*)&Ws[nx][(w_k + i * 8) * 64 + w_n] = rW[i];
        }
        __syncthreads();
    }

    float4 bv = *(const float4*)&bias[nBase + tx * 4];
    #pragma unroll
    for (int i = 0; i < 4; i++) {
        int row = mBase + ty * 4 + i;
        float4 o;
        o.x = acc[i][0] + bv.x; o.y = acc[i][1] + bv.y;
        o.z = acc[i][2] + bv.z; o.w = acc[i][3] + bv.w;
        *(float4*)&g_vis[(size_t)row * HDIM + nBase + tx * 4] = o;
    }
}

// ---------------- K4: gate logits (2 warps per row) ----------------------
__global__ __launch_bounds__(256) void wsoft_kernel(const float* __restrict__ tag,
                                                    const float* __restrict__ pos,
                                                    const float* __restrict__ Wsoft,
                                                    const float* __restrict__ bsoft) {
    int tid = threadIdx.x;
    int w = tid >> 5, lane = tid & 31;
    int rb = blockIdx.x * 4;                 // 256 blocks, 4 rows each
    int r = rb + (w >> 1);
    int half = w & 1;
    __shared__ float pl[8][2];

    const float4* v = (const float4*)(g_vis + (size_t)r * HDIM);
    const float4* t = (const float4*)(tag + (size_t)r * HDIM);
    const float4* p = (const float4*)(pos + (size_t)r * HDIM);
    const float4* Wq = (const float4*)Wsoft;
    float l0 = 0.f, l1 = 0.f;
    #pragma unroll
    for (int i = 0; i < 2; i++) {
        int h4 = half * 64 + i * 32 + lane;
        float4 a = v[h4], c = t[h4], e = p[h4];
        float s0 = a.x + c.x + e.x, s1 = a.y + c.y + e.y;
        float s2 = a.z + c.z + e.z, s3 = a.w + c.w + e.w;
        float4 w01 = Wq[h4 * 2], w23 = Wq[h4 * 2 + 1];
        l0 += s0 * w01.x + s1 * w01.z + s2 * w23.x + s3 * w23.z;
        l1 += s0 * w01.y + s1 * w01.w + s2 * w23.y + s3 * w23.w;
    }
    #pragma unroll
    for (int o = 16; o; o >>= 1) {
        l0 += __shfl_xor_sync(0xffffffffu, l0, o);
        l1 += __shfl_xor_sync(0xffffffffu, l1, o);
    }
    if (lane == 0) { pl[w][0] = l0; pl[w][1] = l1; }
    __syncthreads();
    if (tid < 4) {
        int rr = rb + tid;
        float L0 = pl[tid * 2][0] + pl[tid * 2 + 1][0];
        float L1 = pl[tid * 2][1] + pl[tid * 2 + 1][1];
        L0 = (L0 + bsoft[0]) / 0.03f;
        L1 = (L1 + bsoft[1]) / 0.03f;
        float m = fmaxf(L0, L1);
        float lse = m + logf(expf(L0 - m) + expf(L1 - m));
        g_w[2 * rr + 0] = L0 - lse;
        g_w[2 * rr + 1] = L1 - lse;
    }
}

// ---------------- K5: vis2 dual GEMM, tile 32x64, BK=16 ------------------
#define G2_BK 16
#define G2_NT (HDIM / G2_BK)
#define YS_STRIDE 20
__global__ __launch_bounds__(128) void gemm2_kernel(
    const float* __restrict__ Wvp, const float* __restrict__ bvp,
    const float* __restrict__ Wtg, const float* __restrict__ btg,
    const float* __restrict__ tag, const float* __restrict__ pos) {
    int mBase = blockIdx.y * 32;
    int nBase = blockIdx.x * 64;
    int tid = threadIdx.x;
    int tx = tid & 15;
    int ty = tid >> 4;

    __shared__ __align__(16) float Xs[2][32 * YS_STRIDE];
    __shared__ __align__(16) float Ys[2][32 * YS_STRIDE];
    __shared__ __align__(16) float Ws[2][G2_BK * 64];
    __shared__ __align__(16) float Vs[2][G2_BK * 64];
    __shared__ float w0s[32], w1s[32];

    // A loads: a_m = tid>>2 (0..31), a_k = (tid&3)*4 (0..12): one float4 each for X,Y
    int a_m = tid >> 2;
    int a_k = (tid & 3) * 4;
    // W loads: l = tid + i*128 (i=0..1): w_k = (tid>>4)+i*8, w_n = (tid&15)*4
    int w_k = tid >> 4;
    int w_n = (tid & 15) * 4;

    const float* Xb = g_vis + (size_t)mBase * HDIM;
    const float* Yb = tag + (size_t)mBase * HDIM;

    float4 rX, rY, rW[2], rV[2];
    rX = *(const float4*)&Xb[(size_t)a_m * HDIM + a_k];
    rY = *(const float4*)&Yb[(size_t)a_m * HDIM + a_k];
    #pragma unroll
    for (int i = 0; i < 2; i++) {
        rW[i] = *(const float4*)&Wvp[(size_t)(w_k + i * 8) * HDIM + nBase + w_n];
        rV[i] = *(const float4*)&Wtg[(size_t)(w_k + i * 8) * HDIM + nBase + w_n];
    }
    if (tid < 32) {
        w0s[tid] = g_w[(mBase + tid) * 2 + 0];
        w1s[tid] = g_w[(mBase + tid) * 2 + 1];
    }
    __syncthreads();   // w0s ready before scaled STS

    {
        float s0 = w0s[a_m], s1 = w1s[a_m];
        float4 x = rX, y = rY;
        x.x *= s0; x.y *= s0; x.z *= s0; x.w *= s0;
        y.x *= s1; y.y *= s1; y.z *= s1; y.w *= s1;
        *(float4*)&Xs[0][a_m * YS_STRIDE + a_k] = x;
        *(float4*)&Ys[0][a_m * YS_STRIDE + a_k] = y;
    }
    #pragma unroll
    for (int i = 0; i < 2; i++) {
        *(float4*)&Ws[0][(w_k + i * 8) * 64 + w_n] = rW[i];
        *(float4*)&Vs[0][(w_k + i * 8) * 64 + w_n] = rV[i];
    }
    __syncthreads();

    float acc[4][4];
    #pragma unroll
    for (int i = 0; i < 4; i++)
        #pragma unroll
        for (int j = 0; j < 4; j++) acc[i][j] = 0.f;

    for (int t = 0; t < G2_NT; t++) {
        int cur = t & 1;
        int k0n = (t + 1) * G2_BK;
        if (t + 1 < G2_NT) {
            rX = *(const float4*)&Xb[(size_t)a_m * HDIM + k0n + a_k];
            rY = *(const float4*)&Yb[(size_t)a_m * HDIM + k0n + a_k];
            #pragma unroll
            for (int i = 0; i < 2; i++) {
                rW[i] = *(const float4*)&Wvp[(size_t)(k0n + w_k + i * 8) * HDIM + nBase + w_n];
                rV[i] = *(const float4*)&Wtg[(size_t)(k0n + w_k + i * 8) * HDIM + nBase + w_n];
            }
        }
        #pragma unroll
        for (int kc = 0; kc < G2_BK / 4; kc++) {
            float4 xv[4], yv[4];
            #pragma unroll
            for (int i = 0; i < 4; i++) {
                xv[i] = *(const float4*)&Xs[cur][(ty * 4 + i) * YS_STRIDE + kc * 4];
                yv[i] = *(const float4*)&Ys[cur][(ty * 4 + i) * YS_STRIDE + kc * 4];
            }
            #pragma unroll
            for (int j = 0; j < 4; j++) {
                float4 wv = *(const float4*)&Ws[cur][(kc * 4 + j) * 64 + tx * 4];
                float4 vv = *(const float4*)&Vs[cur][(kc * 4 + j) * 64 + tx * 4];
                #pragma unroll
                for (int i = 0; i < 4; i++) {
                    float x = (j == 0) ? xv[i].x : (j == 1) ? xv[i].y : (j == 2) ? xv[i].z : xv[i].w;
                    float y = (j == 0) ? yv[i].x : (j == 1) ? yv[i].y : (j == 2) ? yv[i].z : yv[i].w;
                    acc[i][0] += x * wv.x + y * vv.x;
                    acc[i][1] += x * wv.y + y * vv.y;
                    acc[i][2] += x * wv.z + y * vv.z;
                    acc[i][3] += x * wv.w + y * vv.w;
                }
            }
        }
        if (t + 1 < G2_NT) {
            int nx = cur ^ 1;
            float s0 = w0s[a_m], s1 = w1s[a_m];
            float4 x = rX, y = rY;
            x.x *= s0; x.y *= s0; x.z *= s0; x.w *= s0;
            y.x *= s1; y.y *= s1; y.z *= s1; y.w *= s1;
            *(float4*)&Xs[nx][a_m * YS_STRIDE + a_k] = x;
            *(float4*)&Ys[nx][a_m * YS_STRIDE + a_k] = y;
            #pragma unroll
            for (int i = 0; i < 2; i++) {
                *(float4*)&Ws[nx][(w_k + i * 8) * 64 + w_n] = rW[i];
                *(float4*)&Vs[nx][(w_k + i * 8) * 64 + w_n] = rV[i];
            }
        }
        __syncthreads();
    }

    int col = nBase + tx * 4;
    float4 b0;
    {
        float4 a0 = *(const float4*)&bvp[col];
        float4 c0 = *(const float4*)&btg[col];
        b0.x = a0.x + c0.x; b0.y = a0.y + c0.y;
        b0.z = a0.z + c0.z; b0.w = a0.w + c0.w;
    }
    #pragma unroll
    for (int i = 0; i < 4; i++) {
        int row = mBase + ty * 4 + i;
        float4 p0 = *(const float4*)&pos[(size_t)row * HDIM + col];
        float4 o;
        o.x = acc[i][0] + b0.x + p0.x; o.y = acc[i][1] + b0.y + p0.y;
        o.z = acc[i][2] + b0.z + p0.z; o.w = acc[i][3] + b0.w + p0.w;
        *(float4*)&g_vis2[(size_t)row * HDIM + col] = o;
    }
}

// ---------------- K6: language projection + norm (512 thr/blk) -----------
__global__ __launch_bounds__(512) void lang_kernel(const float* __restrict__ lang,
                                                   const float* __restrict__ Wts,
                                                   const float* __restrict__ bts) {
    int b = blockIdx.x, tid = threadIdx.x;   // 512 threads, one output each
    __shared__ float lg[HDIM];
    __shared__ float wr[16];
    lg[tid] = lang[b * HDIM + tid];
    __syncthreads();
    float a = bts[tid];
    #pragma unroll 8
    for (int k = 0; k < HDIM; k++)
        a += lg[k] * Wts[(size_t)k * HDIM + tid];
    g_lang[b * HDIM + tid] = a;
    float q = a * a;
    #pragma unroll
    for (int o = 16; o; o >>= 1) q += __shfl_xor_sync(0xffffffffu, q, o);
    if ((tid & 31) == 0) wr[tid >> 5] = q;
    __syncthreads();
    if (tid < 32) {
        float s = (tid < 16) ? wr[tid] : 0.f;
        #pragma unroll
        for (int o = 8; o; o >>= 1) s += __shfl_xor_sync(0xffffffffu, s, o);
        if (tid == 0) g_ln[b] = sqrtf(s) + EPSF;
    }
}

// ---------------- K7: cosine sim (warp per sel), argmax, box decode ------
__global__ void final_kernel(const float* __restrict__ boxes, float* __restrict__ out) {
    int b = blockIdx.x, tid = threadIdx.x;   // 1024 threads = 32 warps
    int w = tid >> 5, lane = tid & 31;
    __shared__ float ssim[SEL];

    const float4* v2 = (const float4*)(g_vis2 + (size_t)(b * SEL + w) * HDIM);
    const float4* le = (const float4*)(g_lang + (size_t)b * HDIM);
    float d = 0.f, q = 0.f;
    #pragma unroll
    for (int i = 0; i < 4; i++) {
        float4 a = v2[lane + i * 32];
        float4 c = le[lane + i * 32];
        d += a.x * c.x + a.y * c.y + a.z * c.z + a.w * c.w;
        q += a.x * a.x + a.y * a.y + a.z * a.z + a.w * a.w;
    }
    #pragma unroll
    for (int o = 16; o; o >>= 1) {
        d += __shfl_xor_sync(0xffffffffu, d, o);
        q += __shfl_xor_sync(0xffffffffu, q, o);
    }
    if (lane == 0) ssim[w] = d / ((sqrtf(q) + EPSF) * g_ln[b]);
    __syncthreads();

    if (tid < SEL) out[BS * 5 + b * SEL + tid] = ssim[tid];

    if (w == 0) {
        float v = ssim[lane]; int bi = lane;
        #pragma unroll
        for (int o = 16; o; o >>= 1) {
            float ov = __shfl_down_sync(0xffffffffu, v, o);
            int   oi = __shfl_down_sync(0xffffffffu, bi, o);
            if (ov > v || (ov == v && oi < bi)) { v = ov; bi = oi; }
        }
        if (lane == 0) {
            int g = g_idx[b * SEL + bi];
            const float* base = boxes + ((size_t)b * GRID_N + g) * A_N * CH;
            int j = 0; float ov = base[4];
            for (int a = 1; a < A_N; a++) {
                float o2 = base[a * CH + 4];
                if (o2 > ov) { ov = o2; j = a; }
            }
            float x = base[j * CH + 0], y = base[j * CH + 1];
            float wd = base[j * CH + 2], hh = base[j * CH + 3];
            float x1 = x - wd * 0.5f, y1 = y - hh * 0.5f;
            out[b * 5 + 0] = x1;
            out[b * 5 + 1] = y1;
            out[b * 5 + 2] = x1 + wd;
            out[b * 5 + 3] = y1 + hh;
            out[b * 5 + 4] = ov;
        }
    }
}

// ---------------- launch --------------------------------------------------
extern "C" void kernel_launch(void* const* d_in, const int* in_sizes, int n_in,
                              void* d_out, int out_size) {
    const float* boxes    = (const float*)d_in[0];
    const float* x_feat   = (const float*)d_in[1];
    const float* tag_emb  = (const float*)d_in[2];
    const float* pos_emb  = (const float*)d_in[3];
    const float* lang     = (const float*)d_in[4];
    const float* W_vs     = (const float*)d_in[5];
    const float* b_vs     = (const float*)d_in[6];
    const float* W_ts     = (const float*)d_in[7];
    const float* b_ts     = (const float*)d_in[8];
    const float* W_vs_pos = (const float*)d_in[9];
    const float* b_vs_pos = (const float*)d_in[10];
    const float* W_tag    = (const float*)d_in[11];
    const float* b_tag    = (const float*)d_in[12];
    const float* W_soft   = (const float*)d_in[13];
    const float* b_soft   = (const float*)d_in[14];
    float* out = (float*)d_out;

    topk_kernel<<<BS, 256>>>(boxes);
    gather_kernel<<<BS * SEL, 256>>>(x_feat);
    lang_kernel<<<BS, 512>>>(lang, W_ts, b_ts);
    gemm1_kernel<<<dim3(HDIM / 64, ROWS / 32), 128>>>(W_vs, b_vs);
    wsoft_kernel<<<ROWS / 4, 256>>>(tag_emb, pos_emb, W_soft, b_soft);
    gemm2_kernel<<<dim3(HDIM / 64, ROWS / 32), 128>>>(W_vs_pos, b_vs_pos, W_tag, b_tag, tag_emb, pos_emb);
    final_kernel<<<BS, 1024>>>(boxes, out);
}

// round 7
// speedup vs baseline: 1.3133x; 1.0625x over previous
#include <cuda_runtime.h>
#include <math.h>
#include <stdint.h>

#define BS     32
#define GRID_N 2704
#define A_N    3
#define CH     85
#define VDIM   1024
#define HDIM   512
#define SEL    32
#define ROWS   (BS * SEL)          // 1024 flattened rows
#define EPSF   1e-8f

// ---------------- device scratch (static, no allocation) ----------------
__device__ int   g_idx[BS * SEL];
__device__ float g_isel[(size_t)ROWS * VDIM];
__device__ float g_vis[(size_t)ROWS * HDIM];
__device__ float g_w[ROWS * 2];
__device__ float g_vis2[(size_t)ROWS * HDIM];
__device__ float g_lang[BS * HDIM];
__device__ float g_ln[BS];

// ---------------- tf32 mma helpers ---------------------------------------
__device__ __forceinline__ uint32_t f2tf(float x) {
    uint32_t r;
    asm("cvt.rna.tf32.f32 %0, %1;" : "=r"(r) : "f"(x));
    return r;
}
__device__ __forceinline__ void split_tf(float x, uint32_t& hi, uint32_t& lo) {
    hi = f2tf(x);
    lo = f2tf(x - __uint_as_float(hi));
}
__device__ __forceinline__ void mma8(float d[4], const uint32_t a[4], const uint32_t b[2]) {
    asm volatile(
        "mma.sync.aligned.m16n8k8.row.col.f32.tf32.tf32.f32 "
        "{%0,%1,%2,%3}, {%4,%5,%6,%7}, {%8,%9}, {%0,%1,%2,%3};"
        : "+f"(d[0]), "+f"(d[1]), "+f"(d[2]), "+f"(d[3])
        : "r"(a[0]), "r"(a[1]), "r"(a[2]), "r"(a[3]), "r"(b[0]), "r"(b[1]));
}

// ---------------- K1: objectness score + exact top-32 via histogram ------
__global__ void topk_kernel(const float* __restrict__ boxes) {
    int b = blockIdx.x;
    int tid = threadIdx.x;          // 256 threads
    __shared__ float sc[GRID_N];
    __shared__ int   hist[512];
    __shared__ int   s_binB, s_definite;
    __shared__ int   cnt_hi, cnt_cb, overflow;
    __shared__ int   hi_idx[SEL];
    __shared__ float cb_sc[512];
    __shared__ int   cb_idx[512];
    __shared__ int   sel[SEL];
    __shared__ float rv[8];
    __shared__ int   ri[8];

    for (int i = tid; i < 512; i += 256) hist[i] = 0;
    if (tid == 0) { cnt_hi = 0; cnt_cb = 0; overflow = 0; }
    __syncthreads();

    const float* bb = boxes + (size_t)b * GRID_N * A_N * CH;
    for (int g = tid; g < GRID_N; g += 256) {
        const float* p = bb + (size_t)g * A_N * CH;
        float s = (p[4] + p[CH + 4] + p[2 * CH + 4]) * (1.0f / 3.0f);
        sc[g] = s;
        int bin = (int)(s * 512.0f);
        bin = max(0, min(511, bin));
        atomicAdd(&hist[bin], 1);
    }
    __syncthreads();

    if (tid == 0) {
        int cum = 0, bB = 0, def = 0;
        for (int v = 511; v >= 0; v--) {
            cum += hist[v];
            if (cum >= SEL) { bB = v; def = cum - hist[v]; break; }
        }
        s_binB = bB; s_definite = def;
    }
    __syncthreads();
    int binB = s_binB;

    for (int g = tid; g < GRID_N; g += 256) {
        float s = sc[g];
        int bin = (int)(s * 512.0f);
        bin = max(0, min(511, bin));
        if (bin > binB) {
            int p = atomicAdd(&cnt_hi, 1);
            hi_idx[p] = g;
        } else if (bin == binB) {
            int p = atomicAdd(&cnt_cb, 1);
            if (p < 512) { cb_sc[p] = s; cb_idx[p] = g; }
            else overflow = 1;
        }
    }
    __syncthreads();

    if (!overflow) {
        if (tid >= 32 && (tid - 32) < s_definite) sel[tid - 32] = hi_idx[tid - 32];
        if (tid < 32) {
            int need = SEL - s_definite;
            int n = min(cnt_cb, 512);
            for (int it = 0; it < need; it++) {
                float best = -1e30f; int bi = GRID_N;
                for (int c = tid; c < n; c += 32) {
                    float v = cb_sc[c]; int gi = cb_idx[c];
                    if (v > best || (v == best && gi < bi)) { best = v; bi = gi; }
                }
                #pragma unroll
                for (int o = 16; o; o >>= 1) {
                    float ov = __shfl_down_sync(0xffffffffu, best, o);
                    int   oi = __shfl_down_sync(0xffffffffu, bi, o);
                    if (ov > best || (ov == best && oi < bi)) { best = ov; bi = oi; }
                }
                bi = __shfl_sync(0xffffffffu, bi, 0);
                if (tid == 0) sel[s_definite + it] = bi;
                for (int c = tid; c < n; c += 32)
                    if (cb_idx[c] == bi) cb_sc[c] = -1e30f;
                __syncwarp();
            }
        }
    }
    __syncthreads();

    if (overflow) {
        for (int it = 0; it < SEL; it++) {
            float best = -1e30f;
            int   bi = GRID_N;
            for (int g = tid; g < GRID_N; g += 256) {
                float v = sc[g];
                if (v > best) { best = v; bi = g; }
            }
            #pragma unroll
            for (int o = 16; o; o >>= 1) {
                float ov = __shfl_down_sync(0xffffffffu, best, o);
                int   oi = __shfl_down_sync(0xffffffffu, bi, o);
                if (ov > best || (ov == best && oi < bi)) { best = ov; bi = oi; }
            }
            if ((tid & 31) == 0) { rv[tid >> 5] = best; ri[tid >> 5] = bi; }
            __syncthreads();
            if (tid == 0) {
                float B = rv[0]; int BI = ri[0];
                for (int w = 1; w < 8; w++)
                    if (rv[w] > B || (rv[w] == B && ri[w] < BI)) { B = rv[w]; BI = ri[w]; }
                sel[it] = BI;
                sc[BI] = -1e30f;
            }
            __syncthreads();
        }
    }

    if (tid == 0) {
        for (int i = 1; i < SEL; i++) {
            int v = sel[i], j = i - 1;
            while (j >= 0 && sel[j] > v) { sel[j + 1] = sel[j]; j--; }
            sel[j + 1] = v;
        }
        for (int i = 0; i < SEL; i++) g_idx[b * SEL + i] = sel[i];
    }
}

// ---------------- K2: gather selected feature columns --------------------
__global__ void gather_kernel(const float* __restrict__ xfeat) {
    int row = blockIdx.x;           // b*SEL + s
    int b = row >> 5;
    int g = g_idx[row];
    const float* src = xfeat + (size_t)b * VDIM * GRID_N + g;
    float* dst = g_isel + (size_t)row * VDIM;
    for (int v = threadIdx.x; v < VDIM; v += blockDim.x)
        dst[v] = __ldg(&src[(size_t)v * GRID_N]);
}

// ---------------- K3: vis = isel @ W_vs + b_vs (3xTF32 tensor cores) -----
// Tile 32(M)x64(N), BK=32, 128 threads = 4 warps in 2x2, warp tile m16n32.
// A smem: [m][k] stride 35 (STS conflict-free, frag LDS <=2-way).
// B smem: [k][n] with XOR swizzle n ^ ((k&3)*8) (conflict-free both ways).
#define G1_BK 32
#define G1_NT (VDIM / G1_BK)
#define XST 35
__global__ __launch_bounds__(128) void gemm1_kernel(const float* __restrict__ W,
                                                    const float* __restrict__ bias) {
    int mBase = blockIdx.y * 32;
    int nBase = blockIdx.x * 64;
    int tid = threadIdx.x;
    int warp = tid >> 5, lane = tid & 31;
    int gid = lane >> 2, tig = lane & 3;
    int wm = (warp & 1) * 16, wn = (warp >> 1) * 32;

    __shared__ float Xs[2][32 * XST];
    __shared__ __align__(16) float Ws[2][G1_BK * 64];

    int a_m = tid >> 3;             // X rows a_m, a_m+16; cols a_k..a_k+3
    int a_k = (tid & 7) * 4;
    int w_k = tid >> 4;             // W k-rows w_k + i*8 (i<4); cols w_n..+3
    int w_n = (tid & 15) * 4;

    const float* Ab = g_isel + (size_t)mBase * VDIM;

    float4 rA[2], rW[4];
    #pragma unroll
    for (int i = 0; i < 2; i++)
        rA[i] = *(const float4*)&Ab[(size_t)(a_m + i * 16) * VDIM + a_k];
    #pragma unroll
    for (int i = 0; i < 4; i++)
        rW[i] = *(const float4*)&W[(size_t)(w_k + i * 8) * HDIM + nBase + w_n];
    #pragma unroll
    for (int i = 0; i < 2; i++) {
        int m = a_m + i * 16;
        Xs[0][m * XST + a_k + 0] = rA[i].x;
        Xs[0][m * XST + a_k + 1] = rA[i].y;
        Xs[0][m * XST + a_k + 2] = rA[i].z;
        Xs[0][m * XST + a_k + 3] = rA[i].w;
    }
    #pragma unroll
    for (int i = 0; i < 4; i++) {
        int k = w_k + i * 8;
        *(float4*)&Ws[0][k * 64 + (w_n ^ ((k & 3) * 8))] = rW[i];
    }
    __syncthreads();

    float acc[4][4];
    #pragma unroll
    for (int j = 0; j < 4; j++)
        #pragma unroll
        for (int r = 0; r < 4; r++) acc[j][r] = 0.f;

    for (int t = 0; t < G1_NT; t++) {
        int cur = t & 1;
        int k0n = (t + 1) * G1_BK;
        if (t + 1 < G1_NT) {
            #pragma unroll
            for (int i = 0; i < 2; i++)
                rA[i] = *(const float4*)&Ab[(size_t)(a_m + i * 16) * VDIM + k0n + a_k];
            #pragma unroll
            for (int i = 0; i < 4; i++)
                rW[i] = *(const float4*)&W[(size_t)(k0n + w_k + i * 8) * HDIM + nBase + w_n];
        }
        #pragma unroll
        for (int kb = 0; kb < G1_BK; kb += 8) {
            float af[4];
            af[0] = Xs[cur][(wm + gid) * XST + kb + tig];
            af[1] = Xs[cur][(wm + gid + 8) * XST + kb + tig];
            af[2] = Xs[cur][(wm + gid) * XST + kb + tig + 4];
            af[3] = Xs[cur][(wm + gid + 8) * XST + kb + tig + 4];
            uint32_t ah[4], al[4];
            #pragma unroll
            for (int r = 0; r < 4; r++) split_tf(af[r], ah[r], al[r]);
            #pragma unroll
            for (int j = 0; j < 4; j++) {
                int n0 = wn + j * 8;
                int sw = (n0 + gid) ^ (tig * 8);
                float bf0 = Ws[cur][(kb + tig) * 64 + sw];
                float bf1 = Ws[cur][(kb + tig + 4) * 64 + sw];
                uint32_t bh[2], bl[2];
                split_tf(bf0, bh[0], bl[0]);
                split_tf(bf1, bh[1], bl[1]);
                mma8(acc[j], ah, bh);
                mma8(acc[j], ah, bl);
                mma8(acc[j], al, bh);
            }
        }
        if (t + 1 < G1_NT) {
            int nx = cur ^ 1;
            #pragma unroll
            for (int i = 0; i < 2; i++) {
                int m = a_m + i * 16;
                Xs[nx][m * XST + a_k + 0] = rA[i].x;
                Xs[nx][m * XST + a_k + 1] = rA[i].y;
                Xs[nx][m * XST + a_k + 2] = rA[i].z;
                Xs[nx][m * XST + a_k + 3] = rA[i].w;
            }
            #pragma unroll
            for (int i = 0; i < 4; i++) {
                int k = w_k + i * 8;
                *(float4*)&Ws[nx][k * 64 + (w_n ^ ((k & 3) * 8))] = rW[i];
            }
        }
        __syncthreads();
    }

    int row0 = mBase + wm + gid;
    #pragma unroll
    for (int j = 0; j < 4; j++) {
        int col = nBase + wn + j * 8 + 2 * tig;
        float b0 = bias[col], b1 = bias[col + 1];
        float2 o0 = make_float2(acc[j][0] + b0, acc[j][1] + b1);
        float2 o1 = make_float2(acc[j][2] + b0, acc[j][3] + b1);
        *(float2*)&g_vis[(size_t)row0 * HDIM + col] = o0;
        *(float2*)&g_vis[(size_t)(row0 + 8) * HDIM + col] = o1;
    }
}

// ---------------- K4: gate logits (2 warps per row) ----------------------
__global__ __launch_bounds__(256) void wsoft_kernel(const float* __restrict__ tag,
                                                    const float* __restrict__ pos,
                                                    const float* __restrict__ Wsoft,
                                                    const float* __restrict__ bsoft) {
    int tid = threadIdx.x;
    int w = tid >> 5, lane = tid & 31;
    int rb = blockIdx.x * 4;                 // 256 blocks, 4 rows each
    int r = rb + (w >> 1);
    int half = w & 1;
    __shared__ float pl[8][2];

    const float4* v = (const float4*)(g_vis + (size_t)r * HDIM);
    const float4* t = (const float4*)(tag + (size_t)r * HDIM);
    const float4* p = (const float4*)(pos + (size_t)r * HDIM);
    const float4* Wq = (const float4*)Wsoft;
    float l0 = 0.f, l1 = 0.f;
    #pragma unroll
    for (int i = 0; i < 2; i++) {
        int h4 = half * 64 + i * 32 + lane;
        float4 a = v[h4], c = t[h4], e = p[h4];
        float s0 = a.x + c.x + e.x, s1 = a.y + c.y + e.y;
        float s2 = a.z + c.z + e.z, s3 = a.w + c.w + e.w;
        float4 w01 = Wq[h4 * 2], w23 = Wq[h4 * 2 + 1];
        l0 += s0 * w01.x + s1 * w01.z + s2 * w23.x + s3 * w23.z;
        l1 += s0 * w01.y + s1 * w01.w + s2 * w23.y + s3 * w23.w;
    }
    #pragma unroll
    for (int o = 16; o; o >>= 1) {
        l0 += __shfl_xor_sync(0xffffffffu, l0, o);
        l1 += __shfl_xor_sync(0xffffffffu, l1, o);
    }
    if (lane == 0) { pl[w][0] = l0; pl[w][1] = l1; }
    __syncthreads();
    if (tid < 4) {
        int rr = rb + tid;
        float L0 = pl[tid * 2][0] + pl[tid * 2 + 1][0];
        float L1 = pl[tid * 2][1] + pl[tid * 2 + 1][1];
        L0 = (L0 + bsoft[0]) / 0.03f;
        L1 = (L1 + bsoft[1]) / 0.03f;
        float m = fmaxf(L0, L1);
        float lse = m + logf(expf(L0 - m) + expf(L1 - m));
        g_w[2 * rr + 0] = L0 - lse;
        g_w[2 * rr + 1] = L1 - lse;
    }
}

// ---------------- K5: vis2 dual GEMM (3xTF32), tile 32x64, BK=16 ---------
#define G2_BK 16
#define G2_NT (HDIM / G2_BK)
__global__ __launch_bounds__(128) void gemm2_kernel(
    const float* __restrict__ Wvp, const float* __restrict__ bvp,
    const float* __restrict__ Wtg, const float* __restrict__ btg,
    const float* __restrict__ tag, const float* __restrict__ pos) {
    int mBase = blockIdx.y * 32;
    int nBase = blockIdx.x * 64;
    int tid = threadIdx.x;
    int warp = tid >> 5, lane = tid & 31;
    int gid = lane >> 2, tig = lane & 3;
    int wm = (warp & 1) * 16, wn = (warp >> 1) * 32;

    __shared__ float Xs[2][32 * XST], Ys[2][32 * XST];
    __shared__ __align__(16) float Ws[2][G2_BK * 64];
    __shared__ __align__(16) float Vs[2][G2_BK * 64];
    __shared__ float w0s[32], w1s[32];

    int a_m = tid >> 2;             // 0..31, one float4 per thread per array
    int a_k = (tid & 3) * 4;
    int w_k = tid >> 4;             // k rows w_k + i*8 (i<2)
    int w_n = (tid & 15) * 4;

    const float* Xb = g_vis + (size_t)mBase * HDIM;
    const float* Yb = tag + (size_t)mBase * HDIM;

    float4 rX, rY, rW[2], rV[2];
    rX = *(const float4*)&Xb[(size_t)a_m * HDIM + a_k];
    rY = *(const float4*)&Yb[(size_t)a_m * HDIM + a_k];
    #pragma unroll
    for (int i = 0; i < 2; i++) {
        rW[i] = *(const float4*)&Wvp[(size_t)(w_k + i * 8) * HDIM + nBase + w_n];
        rV[i] = *(const float4*)&Wtg[(size_t)(w_k + i * 8) * HDIM + nBase + w_n];
    }
    if (tid < 32) {
        w0s[tid] = g_w[(mBase + tid) * 2 + 0];
        w1s[tid] = g_w[(mBase + tid) * 2 + 1];
    }
    __syncthreads();

    {
        float s0 = w0s[a_m], s1 = w1s[a_m];
        Xs[0][a_m * XST + a_k + 0] = rX.x * s0;
        Xs[0][a_m * XST + a_k + 1] = rX.y * s0;
        Xs[0][a_m * XST + a_k + 2] = rX.z * s0;
        Xs[0][a_m * XST + a_k + 3] = rX.w * s0;
        Ys[0][a_m * XST + a_k + 0] = rY.x * s1;
        Ys[0][a_m * XST + a_k + 1] = rY.y * s1;
        Ys[0][a_m * XST + a_k + 2] = rY.z * s1;
        Ys[0][a_m * XST + a_k + 3] = rY.w * s1;
    }
    #pragma unroll
    for (int i = 0; i < 2; i++) {
        int k = w_k + i * 8;
        *(float4*)&Ws[0][k * 64 + (w_n ^ ((k & 3) * 8))] = rW[i];
        *(float4*)&Vs[0][k * 64 + (w_n ^ ((k & 3) * 8))] = rV[i];
    }
    __syncthreads();

    float acc[4][4];
    #pragma unroll
    for (int j = 0; j < 4; j++)
        #pragma unroll
        for (int r = 0; r < 4; r++) acc[j][r] = 0.f;

    for (int t = 0; t < G2_NT; t++) {
        int cur = t & 1;
        int k0n = (t + 1) * G2_BK;
        if (t + 1 < G2_NT) {
            rX = *(const float4*)&Xb[(size_t)a_m * HDIM + k0n + a_k];
            rY = *(const float4*)&Yb[(size_t)a_m * HDIM + k0n + a_k];
            #pragma unroll
            for (int i = 0; i < 2; i++) {
                rW[i] = *(const float4*)&Wvp[(size_t)(k0n + w_k + i * 8) * HDIM + nBase + w_n];
                rV[i] = *(const float4*)&Wtg[(size_t)(k0n + w_k + i * 8) * HDIM + nBase + w_n];
            }
        }
        #pragma unroll
        for (int kb = 0; kb < G2_BK; kb += 8) {
            float xf[4], yf[4];
            xf[0] = Xs[cur][(wm + gid) * XST + kb + tig];
            xf[1] = Xs[cur][(wm + gid + 8) * XST + kb + tig];
            xf[2] = Xs[cur][(wm + gid) * XST + kb + tig + 4];
            xf[3] = Xs[cur][(wm + gid + 8) * XST + kb + tig + 4];
            yf[0] = Ys[cur][(wm + gid) * XST + kb + tig];
            yf[1] = Ys[cur][(wm + gid + 8) * XST + kb + tig];
            yf[2] = Ys[cur][(wm + gid) * XST + kb + tig + 4];
            yf[3] = Ys[cur][(wm + gid + 8) * XST + kb + tig + 4];
            uint32_t xh[4], xl[4], yh[4], yl[4];
            #pragma unroll
            for (int r = 0; r < 4; r++) {
                split_tf(xf[r], xh[r], xl[r]);
                split_tf(yf[r], yh[r], yl[r]);
            }
            #pragma unroll
            for (int j = 0; j < 4; j++) {
                int n0 = wn + j * 8;
                int sw = (n0 + gid) ^ (tig * 8);
                float wf0 = Ws[cur][(kb + tig) * 64 + sw];
                float wf1 = Ws[cur][(kb + tig + 4) * 64 + sw];
                float vf0 = Vs[cur][(kb + tig) * 64 + sw];
                float vf1 = Vs[cur][(kb + tig + 4) * 64 + sw];
                uint32_t wh[2], wl[2], vh[2], vl[2];
                split_tf(wf0, wh[0], wl[0]);
                split_tf(wf1, wh[1], wl[1]);
                split_tf(vf0, vh[0], vl[0]);
                split_tf(vf1, vh[1], vl[1]);
                mma8(acc[j], xh, wh);
                mma8(acc[j], xh, wl);
                mma8(acc[j], xl, wh);
                mma8(acc[j], yh, vh);
                mma8(acc[j], yh, vl);
                mma8(acc[j], yl, vh);
            }
        }
        if (t + 1 < G2_NT) {
            int nx = cur ^ 1;
            float s0 = w0s[a_m], s1 = w1s[a_m];
            Xs[nx][a_m * XST + a_k + 0] = rX.x * s0;
            Xs[nx][a_m * XST + a_k + 1] = rX.y * s0;
            Xs[nx][a_m * XST + a_k + 2] = rX.z * s0;
            Xs[nx][a_m * XST + a_k + 3] = rX.w * s0;
            Ys[nx][a_m * XST + a_k + 0] = rY.x * s1;
            Ys[nx][a_m * XST + a_k + 1] = rY.y * s1;
            Ys[nx][a_m * XST + a_k + 2] = rY.z * s1;
            Ys[nx][a_m * XST + a_k + 3] = rY.w * s1;
            #pragma unroll
            for (int i = 0; i < 2; i++) {
                int k = w_k + i * 8;
                *(float4*)&Ws[nx][k * 64 + (w_n ^ ((k & 3) * 8))] = rW[i];
                *(float4*)&Vs[nx][k * 64 + (w_n ^ ((k & 3) * 8))] = rV[i];
            }
        }
        __syncthreads();
    }

    int row0 = mBase + wm + gid;
    #pragma unroll
    for (int j = 0; j < 4; j++) {
        int col = nBase + wn + j * 8 + 2 * tig;
        float b0 = bvp[col] + btg[col];
        float b1 = bvp[col + 1] + btg[col + 1];
        float2 p0 = *(const float2*)&pos[(size_t)row0 * HDIM + col];
        float2 p1 = *(const float2*)&pos[(size_t)(row0 + 8) * HDIM + col];
        float2 o0 = make_float2(acc[j][0] + b0 + p0.x, acc[j][1] + b1 + p0.y);
        float2 o1 = make_float2(acc[j][2] + b0 + p1.x, acc[j][3] + b1 + p1.y);
        *(float2*)&g_vis2[(size_t)row0 * HDIM + col] = o0;
        *(float2*)&g_vis2[(size_t)(row0 + 8) * HDIM + col] = o1;
    }
}

// ---------------- K6: language projection + norm (512 thr/blk) -----------
__global__ __launch_bounds__(512) void lang_kernel(const float* __restrict__ lang,
                                                   const float* __restrict__ Wts,
                                                   const float* __restrict__ bts) {
    int b = blockIdx.x, tid = threadIdx.x;   // 512 threads, one output each
    __shared__ float lg[HDIM];
    __shared__ float wr[16];
    lg[tid] = lang[b * HDIM + tid];
    __syncthreads();
    float a = bts[tid];
    #pragma unroll 8
    for (int k = 0; k < HDIM; k++)
        a += lg[k] * Wts[(size_t)k * HDIM + tid];
    g_lang[b * HDIM + tid] = a;
    float q = a * a;
    #pragma unroll
    for (int o = 16; o; o >>= 1) q += __shfl_xor_sync(0xffffffffu, q, o);
    if ((tid & 31) == 0) wr[tid >> 5] = q;
    __syncthreads();
    if (tid < 32) {
        float s = (tid < 16) ? wr[tid] : 0.f;
        #pragma unroll
        for (int o = 8; o; o >>= 1) s += __shfl_xor_sync(0xffffffffu, s, o);
        if (tid == 0) g_ln[b] = sqrtf(s) + EPSF;
    }
}

// ---------------- K7: cosine sim (warp per sel), argmax, box decode ------
__global__ void final_kernel(const float* __restrict__ boxes, float* __restrict__ out) {
    int b = blockIdx.x, tid = threadIdx.x;   // 1024 threads = 32 warps
    int w = tid >> 5, lane = tid & 31;
    __shared__ float ssim[SEL];

    const float4* v2 = (const float4*)(g_vis2 + (size_t)(b * SEL + w) * HDIM);
    const float4* le = (const float4*)(g_lang + (size_t)b * HDIM);
    float d = 0.f, q = 0.f;
    #pragma unroll
    for (int i = 0; i < 4; i++) {
        float4 a = v2[lane + i * 32];
        float4 c = le[lane + i * 32];
        d += a.x * c.x + a.y * c.y + a.z * c.z + a.w * c.w;
        q += a.x * a.x + a.y * a.y + a.z * a.z + a.w * a.w;
    }
    #pragma unroll
    for (int o = 16; o; o >>= 1) {
        d += __shfl_xor_sync(0xffffffffu, d, o);
        q += __shfl_xor_sync(0xffffffffu, q, o);
    }
    if (lane == 0) ssim[w] = d / ((sqrtf(q) + EPSF) * g_ln[b]);
    __syncthreads();

    if (tid < SEL) out[BS * 5 + b * SEL + tid] = ssim[tid];

    if (w == 0) {
        float v = ssim[lane]; int bi = lane;
        #pragma unroll
        for (int o = 16; o; o >>= 1) {
            float ov = __shfl_down_sync(0xffffffffu, v, o);
            int   oi = __shfl_down_sync(0xffffffffu, bi, o);
            if (ov > v || (ov == v && oi < bi)) { v = ov; bi = oi; }
        }
        if (lane == 0) {
            int g = g_idx[b * SEL + bi];
            const float* base = boxes + ((size_t)b * GRID_N + g) * A_N * CH;
            int j = 0; float ov = base[4];
            for (int a = 1; a < A_N; a++) {
                float o2 = base[a * CH + 4];
                if (o2 > ov) { ov = o2; j = a; }
            }
            float x = base[j * CH + 0], y = base[j * CH + 1];
            float wd = base[j * CH + 2], hh = base[j * CH + 3];
            float x1 = x - wd * 0.5f, y1 = y - hh * 0.5f;
            out[b * 5 + 0] = x1;
            out[b * 5 + 1] = y1;
            out[b * 5 + 2] = x1 + wd;
            out[b * 5 + 3] = y1 + hh;
            out[b * 5 + 4] = ov;
        }
    }
}

// ---------------- launch --------------------------------------------------
extern "C" void kernel_launch(void* const* d_in, const int* in_sizes, int n_in,
                              void* d_out, int out_size) {
    const float* boxes    = (const float*)d_in[0];
    const float* x_feat   = (const float*)d_in[1];
    const float* tag_emb  = (const float*)d_in[2];
    const float* pos_emb  = (const float*)d_in[3];
    const float* lang     = (const float*)d_in[4];
    const float* W_vs     = (const float*)d_in[5];
    const float* b_vs     = (const float*)d_in[6];
    const float* W_ts     = (const float*)d_in[7];
    const float* b_ts     = (const float*)d_in[8];
    const float* W_vs_pos = (const float*)d_in[9];
    const float* b_vs_pos = (const float*)d_in[10];
    const float* W_tag    = (const float*)d_in[11];
    const float* b_tag    = (const float*)d_in[12];
    const float* W_soft   = (const float*)d_in[13];
    const float* b_soft   = (const float*)d_in[14];
    float* out = (float*)d_out;

    topk_kernel<<<BS, 256>>>(boxes);
    gather_kernel<<<BS * SEL, 256>>>(x_feat);
    lang_kernel<<<BS, 512>>>(lang, W_ts, b_ts);
    gemm1_kernel<<<dim3(HDIM / 64, ROWS / 32), 128>>>(W_vs, b_vs);
    wsoft_kernel<<<ROWS / 4, 256>>>(tag_emb, pos_emb, W_soft, b_soft);
    gemm2_kernel<<<dim3(HDIM / 64, ROWS / 32), 128>>>(W_vs_pos, b_vs_pos, W_tag, b_tag, tag_emb, pos_emb);
    final_kernel<<<BS, 1024>>>(boxes, out);
}

// round 8
// speedup vs baseline: 1.3633x; 1.0380x over previous
#include <cuda_runtime.h>
#include <math.h>
#include <stdint.h>

#define BS     32
#define GRID_N 2704
#define A_N    3
#define CH     85
#define VDIM   1024
#define HDIM   512
#define SEL    32
#define ROWS   (BS * SEL)          // 1024 flattened rows
#define EPSF   1e-8f

// ---------------- device scratch (static, no allocation) ----------------
__device__ int   g_idx[BS * SEL];
__device__ float g_isel[(size_t)ROWS * VDIM];
__device__ float g_vis[(size_t)ROWS * HDIM];
__device__ float g_w[ROWS * 2];
__device__ float g_vis2[(size_t)ROWS * HDIM];
__device__ float g_lang[BS * HDIM];
__device__ float g_ln[BS];

// ---------------- tf32 mma helpers ---------------------------------------
__device__ __forceinline__ uint32_t f2tf(float x) {
    uint32_t r;
    asm("cvt.rna.tf32.f32 %0, %1;" : "=r"(r) : "f"(x));
    return r;
}
__device__ __forceinline__ void split_tf(float x, uint32_t& hi, uint32_t& lo) {
    hi = f2tf(x);
    lo = f2tf(x - __uint_as_float(hi));
}
__device__ __forceinline__ void split4(float4 v, uint4& h, uint4& l) {
    split_tf(v.x, h.x, l.x);
    split_tf(v.y, h.y, l.y);
    split_tf(v.z, h.z, l.z);
    split_tf(v.w, h.w, l.w);
}
__device__ __forceinline__ void mma8(float d[4], const uint32_t a[4], const uint32_t b[2]) {
    asm volatile(
        "mma.sync.aligned.m16n8k8.row.col.f32.tf32.tf32.f32 "
        "{%0,%1,%2,%3}, {%4,%5,%6,%7}, {%8,%9}, {%0,%1,%2,%3};"
        : "+f"(d[0]), "+f"(d[1]), "+f"(d[2]), "+f"(d[3])
        : "r"(a[0]), "r"(a[1]), "r"(a[2]), "r"(a[3]), "r"(b[0]), "r"(b[1]));
}

// ---------------- K1: objectness score + exact top-32 via histogram ------
__global__ void topk_kernel(const float* __restrict__ boxes) {
    int b = blockIdx.x;
    int tid = threadIdx.x;          // 256 threads
    __shared__ float sc[GRID_N];
    __shared__ int   hist[512];
    __shared__ int   s_binB, s_definite;
    __shared__ int   cnt_hi, cnt_cb, overflow;
    __shared__ int   hi_idx[SEL];
    __shared__ float cb_sc[512];
    __shared__ int   cb_idx[512];
    __shared__ int   sel[SEL];
    __shared__ float rv[8];
    __shared__ int   ri[8];

    for (int i = tid; i < 512; i += 256) hist[i] = 0;
    if (tid == 0) { cnt_hi = 0; cnt_cb = 0; overflow = 0; }
    __syncthreads();

    const float* bb = boxes + (size_t)b * GRID_N * A_N * CH;
    for (int g = tid; g < GRID_N; g += 256) {
        const float* p = bb + (size_t)g * A_N * CH;
        float s = (p[4] + p[CH + 4] + p[2 * CH + 4]) * (1.0f / 3.0f);
        sc[g] = s;
        int bin = (int)(s * 512.0f);
        bin = max(0, min(511, bin));
        atomicAdd(&hist[bin], 1);
    }
    __syncthreads();

    if (tid == 0) {
        int cum = 0, bB = 0, def = 0;
        for (int v = 511; v >= 0; v--) {
            cum += hist[v];
            if (cum >= SEL) { bB = v; def = cum - hist[v]; break; }
        }
        s_binB = bB; s_definite = def;
    }
    __syncthreads();
    int binB = s_binB;

    for (int g = tid; g < GRID_N; g += 256) {
        float s = sc[g];
        int bin = (int)(s * 512.0f);
        bin = max(0, min(511, bin));
        if (bin > binB) {
            int p = atomicAdd(&cnt_hi, 1);
            hi_idx[p] = g;
        } else if (bin == binB) {
            int p = atomicAdd(&cnt_cb, 1);
            if (p < 512) { cb_sc[p] = s; cb_idx[p] = g; }
            else overflow = 1;
        }
    }
    __syncthreads();

    if (!overflow) {
        if (tid >= 32 && (tid - 32) < s_definite) sel[tid - 32] = hi_idx[tid - 32];
        if (tid < 32) {
            int need = SEL - s_definite;
            int n = min(cnt_cb, 512);
            for (int it = 0; it < need; it++) {
                float best = -1e30f; int bi = GRID_N;
                for (int c = tid; c < n; c += 32) {
                    float v = cb_sc[c]; int gi = cb_idx[c];
                    if (v > best || (v == best && gi < bi)) { best = v; bi = gi; }
                }
                #pragma unroll
                for (int o = 16; o; o >>= 1) {
                    float ov = __shfl_down_sync(0xffffffffu, best, o);
                    int   oi = __shfl_down_sync(0xffffffffu, bi, o);
                    if (ov > best || (ov == best && oi < bi)) { best = ov; bi = oi; }
                }
                bi = __shfl_sync(0xffffffffu, bi, 0);
                if (tid == 0) sel[s_definite + it] = bi;
                for (int c = tid; c < n; c += 32)
                    if (cb_idx[c] == bi) cb_sc[c] = -1e30f;
                __syncwarp();
            }
        }
    }
    __syncthreads();

    if (overflow) {
        for (int it = 0; it < SEL; it++) {
            float best = -1e30f;
            int   bi = GRID_N;
            for (int g = tid; g < GRID_N; g += 256) {
                float v = sc[g];
                if (v > best) { best = v; bi = g; }
            }
            #pragma unroll
            for (int o = 16; o; o >>= 1) {
                float ov = __shfl_down_sync(0xffffffffu, best, o);
                int   oi = __shfl_down_sync(0xffffffffu, bi, o);
                if (ov > best || (ov == best && oi < bi)) { best = ov; bi = oi; }
            }
            if ((tid & 31) == 0) { rv[tid >> 5] = best; ri[tid >> 5] = bi; }
            __syncthreads();
            if (tid == 0) {
                float B = rv[0]; int BI = ri[0];
                for (int w = 1; w < 8; w++)
                    if (rv[w] > B || (rv[w] == B && ri[w] < BI)) { B = rv[w]; BI = ri[w]; }
                sel[it] = BI;
                sc[BI] = -1e30f;
            }
            __syncthreads();
        }
    }

    if (tid == 0) {
        for (int i = 1; i < SEL; i++) {
            int v = sel[i], j = i - 1;
            while (j >= 0 && sel[j] > v) { sel[j + 1] = sel[j]; j--; }
            sel[j + 1] = v;
        }
        for (int i = 0; i < SEL; i++) g_idx[b * SEL + i] = sel[i];
    }
}

// ---------------- K2: gather selected feature columns --------------------
__global__ void gather_kernel(const float* __restrict__ xfeat) {
    int row = blockIdx.x;           // b*SEL + s
    int b = row >> 5;
    int g = g_idx[row];
    const float* src = xfeat + (size_t)b * VDIM * GRID_N + g;
    float* dst = g_isel + (size_t)row * VDIM;
    for (int v = threadIdx.x; v < VDIM; v += blockDim.x)
        dst[v] = __ldg(&src[(size_t)v * GRID_N]);
}

// ---------------- K3: vis = isel @ W_vs + b_vs (3xTF32, presplit B) ------
// Tile 32(M)x64(N), BK=32, 256 threads = 8 warps (2m x 4n), warp m16n16.
// A smem: [m][k] float, stride 36 (aligned float4 STS, conflict-free LDS).
// B smem: hi/lo tf32 bits, [k][n] XOR swizzle n ^ ((k&3)*8).
#define G1_BK 32
#define G1_NT (VDIM / G1_BK)
#define X1ST 36
__global__ __launch_bounds__(256) void gemm1_kernel(const float* __restrict__ W,
                                                    const float* __restrict__ bias) {
    int mBase = blockIdx.y * 32;
    int nBase = blockIdx.x * 64;
    int tid = threadIdx.x;
    int warp = tid >> 5, lane = tid & 31;
    int gid = lane >> 2, tig = lane & 3;
    int wm = (warp & 1) * 16, wn = (warp >> 1) * 16;

    __shared__ __align__(16) float    Xs[2][32 * X1ST];
    __shared__ __align__(16) uint32_t WsH[2][G1_BK * 64];
    __shared__ __align__(16) uint32_t WsL[2][G1_BK * 64];

    int a_m = tid >> 3;             // 0..31
    int a_k = (tid & 7) * 4;        // 0..28
    int w_k = tid >> 4;             // 0..15 (k rows w_k, w_k+16)
    int w_n = (tid & 15) * 4;

    const float* Ab = g_isel + (size_t)mBase * VDIM;

    float4 rA, rW[2];
    rA = *(const float4*)&Ab[(size_t)a_m * VDIM + a_k];
    #pragma unroll
    for (int i = 0; i < 2; i++)
        rW[i] = *(const float4*)&W[(size_t)(w_k + i * 16) * HDIM + nBase + w_n];

    *(float4*)&Xs[0][a_m * X1ST + a_k] = rA;
    #pragma unroll
    for (int i = 0; i < 2; i++) {
        int k = w_k + i * 16;
        uint4 h, l;
        split4(rW[i], h, l);
        int off = k * 64 + (w_n ^ ((k & 3) * 8));
        *(uint4*)&WsH[0][off] = h;
        *(uint4*)&WsL[0][off] = l;
    }
    __syncthreads();

    float acc[2][4];
    #pragma unroll
    for (int j = 0; j < 2; j++)
        #pragma unroll
        for (int r = 0; r < 4; r++) acc[j][r] = 0.f;

    for (int t = 0; t < G1_NT; t++) {
        int cur = t & 1;
        int k0n = (t + 1) * G1_BK;
        if (t + 1 < G1_NT) {
            rA = *(const float4*)&Ab[(size_t)a_m * VDIM + k0n + a_k];
            #pragma unroll
            for (int i = 0; i < 2; i++)
                rW[i] = *(const float4*)&W[(size_t)(k0n + w_k + i * 16) * HDIM + nBase + w_n];
        }
        #pragma unroll
        for (int kb = 0; kb < G1_BK; kb += 8) {
            float af[4];
            af[0] = Xs[cur][(wm + gid) * X1ST + kb + tig];
            af[1] = Xs[cur][(wm + gid + 8) * X1ST + kb + tig];
            af[2] = Xs[cur][(wm + gid) * X1ST + kb + tig + 4];
            af[3] = Xs[cur][(wm + gid + 8) * X1ST + kb + tig + 4];
            uint32_t ah[4], al[4];
            #pragma unroll
            for (int r = 0; r < 4; r++) split_tf(af[r], ah[r], al[r]);
            #pragma unroll
            for (int j = 0; j < 2; j++) {
                int n0 = wn + j * 8;
                int sw = (n0 + gid) ^ (tig * 8);
                uint32_t bh[2], bl[2];
                bh[0] = WsH[cur][(kb + tig) * 64 + sw];
                bh[1] = WsH[cur][(kb + tig + 4) * 64 + sw];
                bl[0] = WsL[cur][(kb + tig) * 64 + sw];
                bl[1] = WsL[cur][(kb + tig + 4) * 64 + sw];
                mma8(acc[j], ah, bh);
                mma8(acc[j], ah, bl);
                mma8(acc[j], al, bh);
            }
        }
        if (t + 1 < G1_NT) {
            int nx = cur ^ 1;
            *(float4*)&Xs[nx][a_m * X1ST + a_k] = rA;
            #pragma unroll
            for (int i = 0; i < 2; i++) {
                int k = w_k + i * 16;
                uint4 h, l;
                split4(rW[i], h, l);
                int off = k * 64 + (w_n ^ ((k & 3) * 8));
                *(uint4*)&WsH[nx][off] = h;
                *(uint4*)&WsL[nx][off] = l;
            }
        }
        __syncthreads();
    }

    int row0 = mBase + wm + gid;
    #pragma unroll
    for (int j = 0; j < 2; j++) {
        int col = nBase + wn + j * 8 + 2 * tig;
        float b0 = bias[col], b1 = bias[col + 1];
        float2 o0 = make_float2(acc[j][0] + b0, acc[j][1] + b1);
        float2 o1 = make_float2(acc[j][2] + b0, acc[j][3] + b1);
        *(float2*)&g_vis[(size_t)row0 * HDIM + col] = o0;
        *(float2*)&g_vis[(size_t)(row0 + 8) * HDIM + col] = o1;
    }
}

// ---------------- K4: gate logits (2 warps per row) ----------------------
__global__ __launch_bounds__(256) void wsoft_kernel(const float* __restrict__ tag,
                                                    const float* __restrict__ pos,
                                                    const float* __restrict__ Wsoft,
                                                    const float* __restrict__ bsoft) {
    int tid = threadIdx.x;
    int w = tid >> 5, lane = tid & 31;
    int rb = blockIdx.x * 4;                 // 256 blocks, 4 rows each
    int r = rb + (w >> 1);
    int half = w & 1;
    __shared__ float pl[8][2];

    const float4* v = (const float4*)(g_vis + (size_t)r * HDIM);
    const float4* t = (const float4*)(tag + (size_t)r * HDIM);
    const float4* p = (const float4*)(pos + (size_t)r * HDIM);
    const float4* Wq = (const float4*)Wsoft;
    float l0 = 0.f, l1 = 0.f;
    #pragma unroll
    for (int i = 0; i < 2; i++) {
        int h4 = half * 64 + i * 32 + lane;
        float4 a = v[h4], c = t[h4], e = p[h4];
        float s0 = a.x + c.x + e.x, s1 = a.y + c.y + e.y;
        float s2 = a.z + c.z + e.z, s3 = a.w + c.w + e.w;
        float4 w01 = Wq[h4 * 2], w23 = Wq[h4 * 2 + 1];
        l0 += s0 * w01.x + s1 * w01.z + s2 * w23.x + s3 * w23.z;
        l1 += s0 * w01.y + s1 * w01.w + s2 * w23.y + s3 * w23.w;
    }
    #pragma unroll
    for (int o = 16; o; o >>= 1) {
        l0 += __shfl_xor_sync(0xffffffffu, l0, o);
        l1 += __shfl_xor_sync(0xffffffffu, l1, o);
    }
    if (lane == 0) { pl[w][0] = l0; pl[w][1] = l1; }
    __syncthreads();
    if (tid < 4) {
        int rr = rb + tid;
        float L0 = pl[tid * 2][0] + pl[tid * 2 + 1][0];
        float L1 = pl[tid * 2][1] + pl[tid * 2 + 1][1];
        L0 = (L0 + bsoft[0]) / 0.03f;
        L1 = (L1 + bsoft[1]) / 0.03f;
        float m = fmaxf(L0, L1);
        float lse = m + logf(expf(L0 - m) + expf(L1 - m));
        g_w[2 * rr + 0] = L0 - lse;
        g_w[2 * rr + 1] = L1 - lse;
    }
}

// ---------------- K5: vis2 dual GEMM (3xTF32, presplit W/V) --------------
// Tile 32x64, BK=16, 256 threads = 8 warps, warp m16n16.
#define G2_BK 16
#define G2_NT (HDIM / G2_BK)
#define X2ST 20
__global__ __launch_bounds__(256) void gemm2_kernel(
    const float* __restrict__ Wvp, const float* __restrict__ bvp,
    const float* __restrict__ Wtg, const float* __restrict__ btg,
    const float* __restrict__ tag, const float* __restrict__ pos) {
    int mBase = blockIdx.y * 32;
    int nBase = blockIdx.x * 64;
    int tid = threadIdx.x;
    int warp = tid >> 5, lane = tid & 31;
    int gid = lane >> 2, tig = lane & 3;
    int wm = (warp & 1) * 16, wn = (warp >> 1) * 16;

    __shared__ __align__(16) float    Xs[2][32 * X2ST];
    __shared__ __align__(16) float    Ys[2][32 * X2ST];
    __shared__ __align__(16) uint32_t WsH[2][G2_BK * 64];
    __shared__ __align__(16) uint32_t WsL[2][G2_BK * 64];
    __shared__ __align__(16) uint32_t VsH[2][G2_BK * 64];
    __shared__ __align__(16) uint32_t VsL[2][G2_BK * 64];
    __shared__ float w0s[32], w1s[32];

    // A-side: threads 0-127 load X, 128-255 load Y (one float4 each)
    int ahalf = tid >> 7;
    int at = tid & 127;
    int a_m = at >> 2;              // 0..31
    int a_k = (at & 3) * 4;         // 0..12
    // W/V: one float4 each per thread, w_k 0..15 covers BK=16
    int w_k = tid >> 4;
    int w_n = (tid & 15) * 4;

    const float* Ain = (ahalf ? tag + (size_t)mBase * HDIM : g_vis + (size_t)mBase * HDIM);

    float4 rS, rW, rV;
    rS = *(const float4*)&Ain[(size_t)a_m * HDIM + a_k];
    rW = *(const float4*)&Wvp[(size_t)w_k * HDIM + nBase + w_n];
    rV = *(const float4*)&Wtg[(size_t)w_k * HDIM + nBase + w_n];
    if (tid < 32) {
        w0s[tid] = g_w[(mBase + tid) * 2 + 0];
        w1s[tid] = g_w[(mBase + tid) * 2 + 1];
    }
    __syncthreads();   // gate weights visible

    {
        float sc = ahalf ? w1s[a_m] : w0s[a_m];
        float4 s = rS;
        s.x *= sc; s.y *= sc; s.z *= sc; s.w *= sc;
        float* dst = ahalf ? Ys[0] : Xs[0];
        *(float4*)&dst[a_m * X2ST + a_k] = s;
    }
    {
        uint4 h, l;
        int off = w_k * 64 + (w_n ^ ((w_k & 3) * 8));
        split4(rW, h, l);
        *(uint4*)&WsH[0][off] = h;
        *(uint4*)&WsL[0][off] = l;
        split4(rV, h, l);
        *(uint4*)&VsH[0][off] = h;
        *(uint4*)&VsL[0][off] = l;
    }
    __syncthreads();

    float acc[2][4];
    #pragma unroll
    for (int j = 0; j < 2; j++)
        #pragma unroll
        for (int r = 0; r < 4; r++) acc[j][r] = 0.f;

    for (int t = 0; t < G2_NT; t++) {
        int cur = t & 1;
        int k0n = (t + 1) * G2_BK;
        if (t + 1 < G2_NT) {
            rS = *(const float4*)&Ain[(size_t)a_m * HDIM + k0n + a_k];
            rW = *(const float4*)&Wvp[(size_t)(k0n + w_k) * HDIM + nBase + w_n];
            rV = *(const float4*)&Wtg[(size_t)(k0n + w_k) * HDIM + nBase + w_n];
        }
        #pragma unroll
        for (int kb = 0; kb < G2_BK; kb += 8) {
            float xf[4], yf[4];
            xf[0] = Xs[cur][(wm + gid) * X2ST + kb + tig];
            xf[1] = Xs[cur][(wm + gid + 8) * X2ST + kb + tig];
            xf[2] = Xs[cur][(wm + gid) * X2ST + kb + tig + 4];
            xf[3] = Xs[cur][(wm + gid + 8) * X2ST + kb + tig + 4];
            yf[0] = Ys[cur][(wm + gid) * X2ST + kb + tig];
            yf[1] = Ys[cur][(wm + gid + 8) * X2ST + kb + tig];
            yf[2] = Ys[cur][(wm + gid) * X2ST + kb + tig + 4];
            yf[3] = Ys[cur][(wm + gid + 8) * X2ST + kb + tig + 4];
            uint32_t xh[4], xl[4], yh[4], yl[4];
            #pragma unroll
            for (int r = 0; r < 4; r++) {
                split_tf(xf[r], xh[r], xl[r]);
                split_tf(yf[r], yh[r], yl[r]);
            }
            #pragma unroll
            for (int j = 0; j < 2; j++) {
                int n0 = wn + j * 8;
                int sw = (n0 + gid) ^ (tig * 8);
                uint32_t wh[2], wl[2], vh[2], vl[2];
                wh[0] = WsH[cur][(kb + tig) * 64 + sw];
                wh[1] = WsH[cur][(kb + tig + 4) * 64 + sw];
                wl[0] = WsL[cur][(kb + tig) * 64 + sw];
                wl[1] = WsL[cur][(kb + tig + 4) * 64 + sw];
                vh[0] = VsH[cur][(kb + tig) * 64 + sw];
                vh[1] = VsH[cur][(kb + tig + 4) * 64 + sw];
                vl[0] = VsL[cur][(kb + tig) * 64 + sw];
                vl[1] = VsL[cur][(kb + tig + 4) * 64 + sw];
                mma8(acc[j], xh, wh);
                mma8(acc[j], xh, wl);
                mma8(acc[j], xl, wh);
                mma8(acc[j], yh, vh);
                mma8(acc[j], yh, vl);
                mma8(acc[j], yl, vh);
            }
        }
        if (t + 1 < G2_NT) {
            int nx = cur ^ 1;
            float sc = ahalf ? w1s[a_m] : w0s[a_m];
            float4 s = rS;
            s.x *= sc; s.y *= sc; s.z *= sc; s.w *= sc;
            float* dst = ahalf ? Ys[nx] : Xs[nx];
            *(float4*)&dst[a_m * X2ST + a_k] = s;
            uint4 h, l;
            int off = w_k * 64 + (w_n ^ ((w_k & 3) * 8));
            split4(rW, h, l);
            *(uint4*)&WsH[nx][off] = h;
            *(uint4*)&WsL[nx][off] = l;
            split4(rV, h, l);
            *(uint4*)&VsH[nx][off] = h;
            *(uint4*)&VsL[nx][off] = l;
        }
        __syncthreads();
    }

    int row0 = mBase + wm + gid;
    #pragma unroll
    for (int j = 0; j < 2; j++) {
        int col = nBase + wn + j * 8 + 2 * tig;
        float b0 = bvp[col] + btg[col];
        float b1 = bvp[col + 1] + btg[col + 1];
        float2 p0 = *(const float2*)&pos[(size_t)row0 * HDIM + col];
        float2 p1 = *(const float2*)&pos[(size_t)(row0 + 8) * HDIM + col];
        float2 o0 = make_float2(acc[j][0] + b0 + p0.x, acc[j][1] + b1 + p0.y);
        float2 o1 = make_float2(acc[j][2] + b0 + p1.x, acc[j][3] + b1 + p1.y);
        *(float2*)&g_vis2[(size_t)row0 * HDIM + col] = o0;
        *(float2*)&g_vis2[(size_t)(row0 + 8) * HDIM + col] = o1;
    }
}

// ---------------- K6: language projection + norm (512 thr/blk) -----------
__global__ __launch_bounds__(512) void lang_kernel(const float* __restrict__ lang,
                                                   const float* __restrict__ Wts,
                                                   const float* __restrict__ bts) {
    int b = blockIdx.x, tid = threadIdx.x;   // 512 threads, one output each
    __shared__ float lg[HDIM];
    __shared__ float wr[16];
    lg[tid] = lang[b * HDIM + tid];
    __syncthreads();
    float a = bts[tid];
    #pragma unroll 8
    for (int k = 0; k < HDIM; k++)
        a += lg[k] * Wts[(size_t)k * HDIM + tid];
    g_lang[b * HDIM + tid] = a;
    float q = a * a;
    #pragma unroll
    for (int o = 16; o; o >>= 1) q += __shfl_xor_sync(0xffffffffu, q, o);
    if ((tid & 31) == 0) wr[tid >> 5] = q;
    __syncthreads();
    if (tid < 32) {
        float s = (tid < 16) ? wr[tid] : 0.f;
        #pragma unroll
        for (int o = 8; o; o >>= 1) s += __shfl_xor_sync(0xffffffffu, s, o);
        if (tid == 0) g_ln[b] = sqrtf(s) + EPSF;
    }
}

// ---------------- K7: cosine sim (warp per sel), argmax, box decode ------
__global__ void final_kernel(const float* __restrict__ boxes, float* __restrict__ out) {
    int b = blockIdx.x, tid = threadIdx.x;   // 1024 threads = 32 warps
    int w = tid >> 5, lane = tid & 31;
    __shared__ float ssim[SEL];

    const float4* v2 = (const float4*)(g_vis2 + (size_t)(b * SEL + w) * HDIM);
    const float4* le = (const float4*)(g_lang + (size_t)b * HDIM);
    float d = 0.f, q = 0.f;
    #pragma unroll
    for (int i = 0; i < 4; i++) {
        float4 a = v2[lane + i * 32];
        float4 c = le[lane + i * 32];
        d += a.x * c.x + a.y * c.y + a.z * c.z + a.w * c.w;
        q += a.x * a.x + a.y * a.y + a.z * a.z + a.w * a.w;
    }
    #pragma unroll
    for (int o = 16; o; o >>= 1) {
        d += __shfl_xor_sync(0xffffffffu, d, o);
        q += __shfl_xor_sync(0xffffffffu, q, o);
    }
    if (lane == 0) ssim[w] = d / ((sqrtf(q) + EPSF) * g_ln[b]);
    __syncthreads();

    if (tid < SEL) out[BS * 5 + b * SEL + tid] = ssim[tid];

    if (w == 0) {
        float v = ssim[lane]; int bi = lane;
        #pragma unroll
        for (int o = 16; o; o >>= 1) {
            float ov = __shfl_down_sync(0xffffffffu, v, o);
            int   oi = __shfl_down_sync(0xffffffffu, bi, o);
            if (ov > v || (ov == v && oi < bi)) { v = ov; bi = oi; }
        }
        if (lane == 0) {
            int g = g_idx[b * SEL + bi];
            const float* base = boxes + ((size_t)b * GRID_N + g) * A_N * CH;
            int j = 0; float ov = base[4];
            for (int a = 1; a < A_N; a++) {
                float o2 = base[a * CH + 4];
                if (o2 > ov) { ov = o2; j = a; }
            }
            float x = base[j * CH + 0], y = base[j * CH + 1];
            float wd = base[j * CH + 2], hh = base[j * CH + 3];
            float x1 = x - wd * 0.5f, y1 = y - hh * 0.5f;
            out[b * 5 + 0] = x1;
            out[b * 5 + 1] = y1;
            out[b * 5 + 2] = x1 + wd;
            out[b * 5 + 3] = y1 + hh;
            out[b * 5 + 4] = ov;
        }
    }
}

// ---------------- launch --------------------------------------------------
extern "C" void kernel_launch(void* const* d_in, const int* in_sizes, int n_in,
                              void* d_out, int out_size) {
    const float* boxes    = (const float*)d_in[0];
    const float* x_feat   = (const float*)d_in[1];
    const float* tag_emb  = (const float*)d_in[2];
    const float* pos_emb  = (const float*)d_in[3];
    const float* lang     = (const float*)d_in[4];
    const float* W_vs     = (const float*)d_in[5];
    const float* b_vs     = (const float*)d_in[6];
    const float* W_ts     = (const float*)d_in[7];
    const float* b_ts     = (const float*)d_in[8];
    const float* W_vs_pos = (const float*)d_in[9];
    const float* b_vs_pos = (const float*)d_in[10];
    const float* W_tag    = (const float*)d_in[11];
    const float* b_tag    = (const float*)d_in[12];
    const float* W_soft   = (const float*)d_in[13];
    const float* b_soft   = (const float*)d_in[14];
    float* out = (float*)d_out;

    topk_kernel<<<BS, 256>>>(boxes);
    gather_kernel<<<BS * SEL, 256>>>(x_feat);
    lang_kernel<<<BS, 512>>>(lang, W_ts, b_ts);
    gemm1_kernel<<<dim3(HDIM / 64, ROWS / 32), 256>>>(W_vs, b_vs);
    wsoft_kernel<<<ROWS / 4, 256>>>(tag_emb, pos_emb, W_soft, b_soft);
    gemm2_kernel<<<dim3(HDIM / 64, ROWS / 32), 256>>>(W_vs_pos, b_vs_pos, W_tag, b_tag, tag_emb, pos_emb);
    final_kernel<<<BS, 1024>>>(boxes, out);
}